// round 1
// baseline (speedup 1.0000x reference)
#include <cuda_runtime.h>
#include <math.h>

#define S_TOK 3120
#define DIM   1536
#define NH    12
#define HD    128
#define FRAME 520   /* H*W = 20*26 */
#define TQ    64
#define TK    64

/* ---- scratch (static device globals; no allocation allowed) ---- */
__device__ float g_q[S_TOK * DIM];
__device__ float g_k[S_TOK * DIM];
__device__ float g_v[S_TOK * DIM];
__device__ float g_o[S_TOK * DIM];

/* ================= GEMM:  C[M,N] = A[M,K] @ W[K,N] + bias ================= */
__global__ __launch_bounds__(256) void gemm_bias_kernel(
    const float* __restrict__ A, const float* __restrict__ W,
    const float* __restrict__ bias, float* __restrict__ C,
    int M, int N, int K)
{
    __shared__ float As[8][128];
    __shared__ float Bs[8][128];

    const int tid = threadIdx.x;
    const int bm = blockIdx.y * 128;
    const int bn = blockIdx.x * 128;
    const int ty = tid >> 4;       /* 0..15 -> row group */
    const int tx = tid & 15;       /* 0..15 -> col group */

    const int a_row = tid >> 1;          /* 0..127 */
    const int a_col = (tid & 1) * 4;     /* 0 or 4 */
    const int b_row = tid >> 5;          /* 0..7   */
    const int b_col = (tid & 31) * 4;    /* 0..124 */

    float acc[8][8];
#pragma unroll
    for (int i = 0; i < 8; i++)
#pragma unroll
        for (int j = 0; j < 8; j++) acc[i][j] = 0.f;

    for (int kk = 0; kk < K; kk += 8) {
        float4 av;
        if (bm + a_row < M) av = *(const float4*)&A[(size_t)(bm + a_row) * K + kk + a_col];
        else                av = make_float4(0.f, 0.f, 0.f, 0.f);
        As[a_col + 0][a_row] = av.x;
        As[a_col + 1][a_row] = av.y;
        As[a_col + 2][a_row] = av.z;
        As[a_col + 3][a_row] = av.w;

        *(float4*)&Bs[b_row][b_col] = *(const float4*)&W[(size_t)(kk + b_row) * N + bn + b_col];
        __syncthreads();

#pragma unroll
        for (int k = 0; k < 8; k++) {
            float ar[8], br[8];
            *(float4*)&ar[0] = *(const float4*)&As[k][ty * 8];
            *(float4*)&ar[4] = *(const float4*)&As[k][ty * 8 + 4];
            *(float4*)&br[0] = *(const float4*)&Bs[k][tx * 8];
            *(float4*)&br[4] = *(const float4*)&Bs[k][tx * 8 + 4];
#pragma unroll
            for (int i = 0; i < 8; i++)
#pragma unroll
                for (int j = 0; j < 8; j++)
                    acc[i][j] += ar[i] * br[j];
        }
        __syncthreads();
    }

    float bv[8];
#pragma unroll
    for (int j = 0; j < 8; j++) bv[j] = bias[bn + tx * 8 + j];

#pragma unroll
    for (int i = 0; i < 8; i++) {
        int r = bm + ty * 8 + i;
        if (r < M) {
            float4 o0 = make_float4(acc[i][0] + bv[0], acc[i][1] + bv[1],
                                    acc[i][2] + bv[2], acc[i][3] + bv[3]);
            float4 o1 = make_float4(acc[i][4] + bv[4], acc[i][5] + bv[5],
                                    acc[i][6] + bv[6], acc[i][7] + bv[7]);
            *(float4*)&C[(size_t)r * N + bn + tx * 8]     = o0;
            *(float4*)&C[(size_t)r * N + bn + tx * 8 + 4] = o1;
        }
    }
}

/* ============ fused RMSNorm (over full DIM) + 3-axis RoPE, in place ============ */
__global__ __launch_bounds__(256) void rms_rope_kernel(
    const float* __restrict__ fcos, const float* __restrict__ fsin,
    const float* __restrict__ gq, const float* __restrict__ gk)
{
    const int row   = blockIdx.x;
    const int which = blockIdx.y;          /* 0 = q, 1 = k */
    float* buf      = which ? g_k : g_q;
    const float* g  = which ? gk : gq;
    const int tid   = threadIdx.x;

    const float* p = buf + (size_t)row * DIM;
    float ss = 0.f;
    for (int i = tid; i < DIM; i += 256) { float v = p[i]; ss += v * v; }

    __shared__ float red[256];
    red[tid] = ss;
    __syncthreads();
    for (int s = 128; s > 0; s >>= 1) {
        if (tid < s) red[tid] += red[tid + s];
        __syncthreads();
    }
    const float inv = rsqrtf(red[0] * (1.0f / DIM) + 1e-6f);

    const int f  = row / FRAME;
    const int hh = (row / 26) % 20;
    const int ww = row % 26;

    /* NH*64 = 768 rotation pairs per row */
    for (int pi = tid; pi < NH * 64; pi += 256) {
        const int head = pi >> 6;
        const int c    = pi & 63;
        const int pr   = (c < 22) ? f : ((c < 43) ? hh : ww);
        const float cs = fcos[pr * 64 + c];
        const float sn = fsin[pr * 64 + c];
        const size_t base = (size_t)row * DIM + head * HD + 2 * c;
        const float xr = buf[base]     * inv * g[head * HD + 2 * c];
        const float xi = buf[base + 1] * inv * g[head * HD + 2 * c + 1];
        buf[base]     = xr * cs - xi * sn;
        buf[base + 1] = xr * sn + xi * cs;
    }
}

/* ================= flash attention with frame-block mask ================= */
/* shared layout (floats): Qs 64*129 | Ks 64*129 | Vs 64*128 | Ps 64*65 | m 64 | l 64 | alpha 64 */
#define SMEM_ATTN_FLOATS (64*129 + 64*129 + 64*128 + 64*65 + 64*3)

__global__ __launch_bounds__(256) void attn_kernel()
{
    extern __shared__ float sm[];
    float* Qs = sm;
    float* Ks = Qs + 64 * 129;
    float* Vs = Ks + 64 * 129;
    float* Ps = Vs + 64 * 128;
    float* sm_m = Ps + 64 * 65;
    float* sm_l = sm_m + 64;
    float* sm_a = sm_l + 64;

    const int tid = threadIdx.x;
    const int h   = blockIdx.y;
    const int qs  = blockIdx.x * TQ;

    /* load Q tile (zero-pad beyond S) */
#pragma unroll
    for (int i = 0; i < 8; i++) {
        int lin = i * 1024 + tid * 4;
        int r = lin >> 7, d = lin & 127;
        float4 v;
        if (qs + r < S_TOK) v = *(const float4*)&g_q[(size_t)(qs + r) * DIM + h * HD + d];
        else                v = make_float4(0.f, 0.f, 0.f, 0.f);
        Qs[r * 129 + d]     = v.x;
        Qs[r * 129 + d + 1] = v.y;
        Qs[r * 129 + d + 2] = v.z;
        Qs[r * 129 + d + 3] = v.w;
    }
    if (tid < 64) { sm_m[tid] = -1e30f; sm_l[tid] = 0.f; }

    float O[8][4];
#pragma unroll
    for (int i = 0; i < 8; i++)
#pragma unroll
        for (int j = 0; j < 4; j++) O[i][j] = 0.f;

    const int ty2 = tid >> 5, tx2 = tid & 31;   /* PV / output mapping */
    const int ty  = tid >> 4, tx  = tid & 15;   /* QK mapping          */

    int fi4[4];
#pragma unroll
    for (int i = 0; i < 4; i++) fi4[i] = (qs + ty * 4 + i) / FRAME;

    const int fi_min = qs / FRAME;
    const int fi_max = min(qs + TQ - 1, S_TOK - 1) / FRAME;
    int lo = fi_min - 3; if (lo < 0) lo = 0;
    lo *= FRAME;
    int hi = (fi_max + 1) * FRAME; if (hi > S_TOK) hi = S_TOK;

    int starts[2], ends[2], nr;
    if (lo <= FRAME) { nr = 1; starts[0] = 0; ends[0] = hi; }
    else { nr = 2; starts[0] = 0; ends[0] = FRAME; starts[1] = (lo / TK) * TK; ends[1] = hi; }

    const float scale = 0.08838834764831845f;   /* 1/sqrt(128) */

    for (int rr = 0; rr < nr; rr++)
    for (int ks = starts[rr]; ks < ends[rr]; ks += TK) {
        __syncthreads();   /* protect Ks/Vs/Ps from previous iteration readers */

        /* load K & V tiles */
#pragma unroll
        for (int i = 0; i < 8; i++) {
            int lin = i * 1024 + tid * 4;
            int r = lin >> 7, d = lin & 127;
            float4 kv, vv;
            if (ks + r < S_TOK) {
                kv = *(const float4*)&g_k[(size_t)(ks + r) * DIM + h * HD + d];
                vv = *(const float4*)&g_v[(size_t)(ks + r) * DIM + h * HD + d];
            } else {
                kv = make_float4(0.f, 0.f, 0.f, 0.f);
                vv = kv;
            }
            Ks[r * 129 + d]     = kv.x;
            Ks[r * 129 + d + 1] = kv.y;
            Ks[r * 129 + d + 2] = kv.z;
            Ks[r * 129 + d + 3] = kv.w;
            *(float4*)&Vs[r * 128 + d] = vv;
        }
        __syncthreads();

        /* QK^T: each thread computes a 4x4 score patch */
        float sacc[4][4];
#pragma unroll
        for (int i = 0; i < 4; i++)
#pragma unroll
            for (int j = 0; j < 4; j++) sacc[i][j] = 0.f;

        for (int d = 0; d < HD; d++) {
            float qr[4], kr[4];
#pragma unroll
            for (int i = 0; i < 4; i++) qr[i] = Qs[(ty * 4 + i) * 129 + d];
#pragma unroll
            for (int j = 0; j < 4; j++) kr[j] = Ks[(tx * 4 + j) * 129 + d];
#pragma unroll
            for (int i = 0; i < 4; i++)
#pragma unroll
                for (int j = 0; j < 4; j++)
                    sacc[i][j] += qr[i] * kr[j];
        }

        /* scale + frame-block mask, write scores to shared */
#pragma unroll
        for (int j = 0; j < 4; j++) {
            const int kg = ks + tx * 4 + j;
            const int fj = kg / FRAME;
#pragma unroll
            for (int i = 0; i < 4; i++) {
                const int fi = fi4[i];
                const bool ok = (kg < S_TOK) && (fj <= fi) && (((fi - fj) < 4) || (fj == 0));
                Ps[(ty * 4 + i) * 65 + tx * 4 + j] = ok ? sacc[i][j] * scale : -1e30f;
            }
        }
        __syncthreads();

        /* online softmax: 4 threads per row, 16 cols each */
        {
            const int row = tid >> 2, sub = tid & 3;
            float mloc = -1e30f;
            for (int c = sub * 16; c < sub * 16 + 16; c++)
                mloc = fmaxf(mloc, Ps[row * 65 + c]);
            mloc = fmaxf(mloc, __shfl_xor_sync(0xffffffffu, mloc, 1));
            mloc = fmaxf(mloc, __shfl_xor_sync(0xffffffffu, mloc, 2));

            const float mold = sm_m[row];
            const float mnew = fmaxf(mold, mloc);

            float lsum = 0.f;
            for (int c = sub * 16; c < sub * 16 + 16; c++) {
                float pv = __expf(Ps[row * 65 + c] - mnew);
                Ps[row * 65 + c] = pv;
                lsum += pv;
            }
            lsum += __shfl_xor_sync(0xffffffffu, lsum, 1);
            lsum += __shfl_xor_sync(0xffffffffu, lsum, 2);

            if (sub == 0) {
                const float a = __expf(mold - mnew);
                sm_a[row] = a;
                sm_m[row] = mnew;
                sm_l[row] = sm_l[row] * a + lsum;
            }
        }
        __syncthreads();

        /* rescale + P@V accumulate. thread -> rows {ty2+8i}, cols tx2*4..+3 */
#pragma unroll
        for (int i = 0; i < 8; i++) {
            const float a = sm_a[ty2 + 8 * i];
            O[i][0] *= a; O[i][1] *= a; O[i][2] *= a; O[i][3] *= a;
        }
        const float4* V4 = (const float4*)Vs;
        for (int j = 0; j < TK; j++) {
            const float4 v = V4[j * 32 + tx2];
#pragma unroll
            for (int i = 0; i < 8; i++) {
                const float pv = Ps[(ty2 + 8 * i) * 65 + j];
                O[i][0] += pv * v.x;
                O[i][1] += pv * v.y;
                O[i][2] += pv * v.z;
                O[i][3] += pv * v.w;
            }
        }
    }
    __syncthreads();

    /* normalize + store */
#pragma unroll
    for (int i = 0; i < 8; i++) {
        const int r = ty2 + 8 * i;
        const int grow = qs + r;
        if (grow < S_TOK) {
            const float inv = 1.f / sm_l[r];
            float4 o = make_float4(O[i][0] * inv, O[i][1] * inv,
                                   O[i][2] * inv, O[i][3] * inv);
            *(float4*)&g_o[(size_t)grow * DIM + h * HD + tx2 * 4] = o;
        }
    }
}

/* ================= launch ================= */
extern "C" void kernel_launch(void* const* d_in, const int* in_sizes, int n_in,
                              void* d_out, int out_size)
{
    const float* x    = (const float*)d_in[0];
    /* d_in[1] seq_lens, d_in[2] grid_sizes: compile-time constants here */
    const float* fcos = (const float*)d_in[3];
    const float* fsin = (const float*)d_in[4];
    const float* Wq = (const float*)d_in[5];  const float* bq = (const float*)d_in[6];
    const float* Wk = (const float*)d_in[7];  const float* bk = (const float*)d_in[8];
    const float* Wv = (const float*)d_in[9];  const float* bv = (const float*)d_in[10];
    const float* Wo = (const float*)d_in[11]; const float* bo = (const float*)d_in[12];
    const float* gq = (const float*)d_in[13]; const float* gk = (const float*)d_in[14];
    float* out = (float*)d_out;

    float *dq, *dk, *dv, *dobuf;
    cudaGetSymbolAddress((void**)&dq,    g_q);
    cudaGetSymbolAddress((void**)&dk,    g_k);
    cudaGetSymbolAddress((void**)&dv,    g_v);
    cudaGetSymbolAddress((void**)&dobuf, g_o);

    const dim3 gemm_grid(DIM / 128, (S_TOK + 127) / 128);   /* (12, 25) */

    gemm_bias_kernel<<<gemm_grid, 256>>>(x, Wq, bq, dq, S_TOK, DIM, DIM);
    gemm_bias_kernel<<<gemm_grid, 256>>>(x, Wk, bk, dk, S_TOK, DIM, DIM);
    gemm_bias_kernel<<<gemm_grid, 256>>>(x, Wv, bv, dv, S_TOK, DIM, DIM);

    rms_rope_kernel<<<dim3(S_TOK, 2), 256>>>(fcos, fsin, gq, gk);

    const int smem_attn = SMEM_ATTN_FLOATS * sizeof(float);   /* ~116 KB */
    cudaFuncSetAttribute(attn_kernel, cudaFuncAttributeMaxDynamicSharedMemorySize, smem_attn);
    attn_kernel<<<dim3((S_TOK + TQ - 1) / TQ, NH), 256, smem_attn>>>();

    gemm_bias_kernel<<<gemm_grid, 256>>>(dobuf, Wo, bo, out, S_TOK, DIM, DIM);
}

// round 2
// speedup vs baseline: 1.3055x; 1.3055x over previous
#include <cuda_runtime.h>
#include <math.h>
#include <stdint.h>

#define S_TOK 3120
#define DIM   1536
#define NH    12
#define HD    128
#define FRAME 520   /* H*W = 20*26 */
#define TQ    64
#define TK    64

/* ---- scratch (static device globals; no allocation allowed) ---- */
__device__ float g_q[S_TOK * DIM];
__device__ float g_k[S_TOK * DIM];
__device__ float g_v[S_TOK * DIM];
__device__ float g_o[S_TOK * DIM];

/* ================= tf32 tensor-core GEMM ================= */
/* C[M,N] = A[M,K] @ W[K,N] + bias,  row-major everywhere.   */
#define BM 128
#define BN 128
#define BK 16

__device__ __forceinline__ uint32_t f2tf32(float x) {
    uint32_t u;
    asm("cvt.rna.tf32.f32 %0, %1;" : "=r"(u) : "f"(x));
    return u;
}

__global__ __launch_bounds__(256, 2) void gemm_tf32_kernel(
    const float* __restrict__ A, const float* __restrict__ W,
    const float* __restrict__ bias, float* __restrict__ C,
    int M, int N, int K)
{
    __shared__ float As[BK][BM + 4];   /* As[k][m], tf32-rounded */
    __shared__ float Bs[BK][BN + 4];   /* Bs[k][n], tf32-rounded */

    const int tid  = threadIdx.x;
    const int warp = tid >> 5;
    const int lane = tid & 31;
    const int r    = lane >> 2;        /* 0..7 */
    const int c    = lane & 3;         /* 0..3 */

    const int bm = blockIdx.y * BM;
    const int bn = blockIdx.x * BN;
    const int wm = (warp & 3) * 32;    /* warp tile 32(m) x 64(n) */
    const int wn = (warp >> 2) * 64;

    float acc[2][8][4];
#pragma unroll
    for (int mi = 0; mi < 2; mi++)
#pragma unroll
        for (int nj = 0; nj < 8; nj++)
#pragma unroll
            for (int e = 0; e < 4; e++) acc[mi][nj][e] = 0.f;

    const int arow = tid >> 1;          /* 0..127 */
    const int acol = (tid & 1) * 8;     /* 0 or 8 */
    const int brow = tid >> 4;          /* 0..15  */
    const int bcol = (tid & 15) * 8;    /* 0..120 */

    for (int kt = 0; kt < K; kt += BK) {
        /* ---- A tile: load 128x16, store transposed [k][m] ---- */
        float4 av0, av1;
        if (bm + arow < M) {
            const float* ap = &A[(size_t)(bm + arow) * K + kt + acol];
            av0 = *(const float4*)ap;
            av1 = *(const float4*)(ap + 4);
        } else {
            av0 = make_float4(0.f, 0.f, 0.f, 0.f);
            av1 = av0;
        }
        As[acol + 0][arow] = __uint_as_float(f2tf32(av0.x));
        As[acol + 1][arow] = __uint_as_float(f2tf32(av0.y));
        As[acol + 2][arow] = __uint_as_float(f2tf32(av0.z));
        As[acol + 3][arow] = __uint_as_float(f2tf32(av0.w));
        As[acol + 4][arow] = __uint_as_float(f2tf32(av1.x));
        As[acol + 5][arow] = __uint_as_float(f2tf32(av1.y));
        As[acol + 6][arow] = __uint_as_float(f2tf32(av1.z));
        As[acol + 7][arow] = __uint_as_float(f2tf32(av1.w));

        /* ---- B tile: 16x128 row-major ---- */
        {
            const float* bp = &W[(size_t)(kt + brow) * N + bn + bcol];
            float4 bv0 = *(const float4*)bp;
            float4 bv1 = *(const float4*)(bp + 4);
            float4 o0 = make_float4(__uint_as_float(f2tf32(bv0.x)), __uint_as_float(f2tf32(bv0.y)),
                                    __uint_as_float(f2tf32(bv0.z)), __uint_as_float(f2tf32(bv0.w)));
            float4 o1 = make_float4(__uint_as_float(f2tf32(bv1.x)), __uint_as_float(f2tf32(bv1.y)),
                                    __uint_as_float(f2tf32(bv1.z)), __uint_as_float(f2tf32(bv1.w)));
            *(float4*)&Bs[brow][bcol]     = o0;
            *(float4*)&Bs[brow][bcol + 4] = o1;
        }
        __syncthreads();

#pragma unroll
        for (int kk = 0; kk < BK; kk += 8) {
            uint32_t af[2][4];
#pragma unroll
            for (int mi = 0; mi < 2; mi++) {
                const int m0 = wm + mi * 16;
                af[mi][0] = __float_as_uint(As[kk + c][m0 + r]);
                af[mi][1] = __float_as_uint(As[kk + c][m0 + r + 8]);
                af[mi][2] = __float_as_uint(As[kk + c + 4][m0 + r]);
                af[mi][3] = __float_as_uint(As[kk + c + 4][m0 + r + 8]);
            }
            uint32_t bf[8][2];
#pragma unroll
            for (int nj = 0; nj < 8; nj++) {
                const int n0 = wn + nj * 8;
                bf[nj][0] = __float_as_uint(Bs[kk + c][n0 + r]);
                bf[nj][1] = __float_as_uint(Bs[kk + c + 4][n0 + r]);
            }
#pragma unroll
            for (int mi = 0; mi < 2; mi++)
#pragma unroll
                for (int nj = 0; nj < 8; nj++) {
                    asm volatile(
                        "mma.sync.aligned.m16n8k8.row.col.f32.tf32.tf32.f32 "
                        "{%0,%1,%2,%3}, {%4,%5,%6,%7}, {%8,%9}, {%0,%1,%2,%3};"
                        : "+f"(acc[mi][nj][0]), "+f"(acc[mi][nj][1]),
                          "+f"(acc[mi][nj][2]), "+f"(acc[mi][nj][3])
                        : "r"(af[mi][0]), "r"(af[mi][1]), "r"(af[mi][2]), "r"(af[mi][3]),
                          "r"(bf[nj][0]), "r"(bf[nj][1]));
                }
        }
        __syncthreads();
    }

    /* ---- epilogue: bias + store ---- */
#pragma unroll
    for (int mi = 0; mi < 2; mi++) {
        const int row0 = bm + wm + mi * 16 + r;
        const int row1 = row0 + 8;
#pragma unroll
        for (int nj = 0; nj < 8; nj++) {
            const int col = bn + wn + nj * 8 + 2 * c;
            const float b0 = bias[col];
            const float b1 = bias[col + 1];
            if (row0 < M) {
                float2 o = make_float2(acc[mi][nj][0] + b0, acc[mi][nj][1] + b1);
                *(float2*)&C[(size_t)row0 * N + col] = o;
            }
            if (row1 < M) {
                float2 o = make_float2(acc[mi][nj][2] + b0, acc[mi][nj][3] + b1);
                *(float2*)&C[(size_t)row1 * N + col] = o;
            }
        }
    }
}

/* ============ fused RMSNorm (over full DIM) + 3-axis RoPE, in place ============ */
__global__ __launch_bounds__(256) void rms_rope_kernel(
    const float* __restrict__ fcos, const float* __restrict__ fsin,
    const float* __restrict__ gq, const float* __restrict__ gk)
{
    const int row   = blockIdx.x;
    const int which = blockIdx.y;          /* 0 = q, 1 = k */
    float* buf      = which ? g_k : g_q;
    const float* g  = which ? gk : gq;
    const int tid   = threadIdx.x;

    const float* p = buf + (size_t)row * DIM;
    float ss = 0.f;
    for (int i = tid; i < DIM; i += 256) { float v = p[i]; ss += v * v; }

    __shared__ float red[256];
    red[tid] = ss;
    __syncthreads();
    for (int s = 128; s > 0; s >>= 1) {
        if (tid < s) red[tid] += red[tid + s];
        __syncthreads();
    }
    const float inv = rsqrtf(red[0] * (1.0f / DIM) + 1e-6f);

    const int f  = row / FRAME;
    const int hh = (row / 26) % 20;
    const int ww = row % 26;

    /* NH*64 = 768 rotation pairs per row */
    for (int pi = tid; pi < NH * 64; pi += 256) {
        const int head = pi >> 6;
        const int c    = pi & 63;
        const int pr   = (c < 22) ? f : ((c < 43) ? hh : ww);
        const float cs = fcos[pr * 64 + c];
        const float sn = fsin[pr * 64 + c];
        const size_t base = (size_t)row * DIM + head * HD + 2 * c;
        const float xr = buf[base]     * inv * g[head * HD + 2 * c];
        const float xi = buf[base + 1] * inv * g[head * HD + 2 * c + 1];
        buf[base]     = xr * cs - xi * sn;
        buf[base + 1] = xr * sn + xi * cs;
    }
}

/* ================= flash attention with frame-block mask ================= */
/* shared layout (floats): Qs 64*129 | Ks 64*129 | Vs 64*128 | Ps 64*65 | m 64 | l 64 | alpha 64 */
#define SMEM_ATTN_FLOATS (64*129 + 64*129 + 64*128 + 64*65 + 64*3)

__global__ __launch_bounds__(256) void attn_kernel()
{
    extern __shared__ float sm[];
    float* Qs = sm;
    float* Ks = Qs + 64 * 129;
    float* Vs = Ks + 64 * 129;
    float* Ps = Vs + 64 * 128;
    float* sm_m = Ps + 64 * 65;
    float* sm_l = sm_m + 64;
    float* sm_a = sm_l + 64;

    const int tid = threadIdx.x;
    const int h   = blockIdx.y;
    const int qs  = blockIdx.x * TQ;

    /* load Q tile (zero-pad beyond S) */
#pragma unroll
    for (int i = 0; i < 8; i++) {
        int lin = i * 1024 + tid * 4;
        int r = lin >> 7, d = lin & 127;
        float4 v;
        if (qs + r < S_TOK) v = *(const float4*)&g_q[(size_t)(qs + r) * DIM + h * HD + d];
        else                v = make_float4(0.f, 0.f, 0.f, 0.f);
        Qs[r * 129 + d]     = v.x;
        Qs[r * 129 + d + 1] = v.y;
        Qs[r * 129 + d + 2] = v.z;
        Qs[r * 129 + d + 3] = v.w;
    }
    if (tid < 64) { sm_m[tid] = -1e30f; sm_l[tid] = 0.f; }

    float O[8][4];
#pragma unroll
    for (int i = 0; i < 8; i++)
#pragma unroll
        for (int j = 0; j < 4; j++) O[i][j] = 0.f;

    const int ty2 = tid >> 5, tx2 = tid & 31;   /* PV / output mapping */
    const int ty  = tid >> 4, tx  = tid & 15;   /* QK mapping          */

    int fi4[4];
#pragma unroll
    for (int i = 0; i < 4; i++) fi4[i] = (qs + ty * 4 + i) / FRAME;

    const int fi_min = qs / FRAME;
    const int fi_max = min(qs + TQ - 1, S_TOK - 1) / FRAME;
    int lo = fi_min - 3; if (lo < 0) lo = 0;
    lo *= FRAME;
    int hi = (fi_max + 1) * FRAME; if (hi > S_TOK) hi = S_TOK;

    int starts[2], ends[2], nr;
    if (lo <= FRAME) { nr = 1; starts[0] = 0; ends[0] = hi; }
    else { nr = 2; starts[0] = 0; ends[0] = FRAME; starts[1] = (lo / TK) * TK; ends[1] = hi; }

    const float scale = 0.08838834764831845f;   /* 1/sqrt(128) */

    for (int rr = 0; rr < nr; rr++)
    for (int ks = starts[rr]; ks < ends[rr]; ks += TK) {
        __syncthreads();   /* protect Ks/Vs/Ps from previous iteration readers */

        /* load K & V tiles */
#pragma unroll
        for (int i = 0; i < 8; i++) {
            int lin = i * 1024 + tid * 4;
            int r = lin >> 7, d = lin & 127;
            float4 kv, vv;
            if (ks + r < S_TOK) {
                kv = *(const float4*)&g_k[(size_t)(ks + r) * DIM + h * HD + d];
                vv = *(const float4*)&g_v[(size_t)(ks + r) * DIM + h * HD + d];
            } else {
                kv = make_float4(0.f, 0.f, 0.f, 0.f);
                vv = kv;
            }
            Ks[r * 129 + d]     = kv.x;
            Ks[r * 129 + d + 1] = kv.y;
            Ks[r * 129 + d + 2] = kv.z;
            Ks[r * 129 + d + 3] = kv.w;
            *(float4*)&Vs[r * 128 + d] = vv;
        }
        __syncthreads();

        /* QK^T: each thread computes a 4x4 score patch */
        float sacc[4][4];
#pragma unroll
        for (int i = 0; i < 4; i++)
#pragma unroll
            for (int j = 0; j < 4; j++) sacc[i][j] = 0.f;

        for (int d = 0; d < HD; d++) {
            float qr[4], kr[4];
#pragma unroll
            for (int i = 0; i < 4; i++) qr[i] = Qs[(ty * 4 + i) * 129 + d];
#pragma unroll
            for (int j = 0; j < 4; j++) kr[j] = Ks[(tx * 4 + j) * 129 + d];
#pragma unroll
            for (int i = 0; i < 4; i++)
#pragma unroll
                for (int j = 0; j < 4; j++)
                    sacc[i][j] += qr[i] * kr[j];
        }

        /* scale + frame-block mask, write scores to shared */
#pragma unroll
        for (int j = 0; j < 4; j++) {
            const int kg = ks + tx * 4 + j;
            const int fj = kg / FRAME;
#pragma unroll
            for (int i = 0; i < 4; i++) {
                const int fi = fi4[i];
                const bool ok = (kg < S_TOK) && (fj <= fi) && (((fi - fj) < 4) || (fj == 0));
                Ps[(ty * 4 + i) * 65 + tx * 4 + j] = ok ? sacc[i][j] * scale : -1e30f;
            }
        }
        __syncthreads();

        /* online softmax: 4 threads per row, 16 cols each */
        {
            const int row = tid >> 2, sub = tid & 3;
            float mloc = -1e30f;
            for (int c = sub * 16; c < sub * 16 + 16; c++)
                mloc = fmaxf(mloc, Ps[row * 65 + c]);
            mloc = fmaxf(mloc, __shfl_xor_sync(0xffffffffu, mloc, 1));
            mloc = fmaxf(mloc, __shfl_xor_sync(0xffffffffu, mloc, 2));

            const float mold = sm_m[row];
            const float mnew = fmaxf(mold, mloc);

            float lsum = 0.f;
            for (int c = sub * 16; c < sub * 16 + 16; c++) {
                float pv = __expf(Ps[row * 65 + c] - mnew);
                Ps[row * 65 + c] = pv;
                lsum += pv;
            }
            lsum += __shfl_xor_sync(0xffffffffu, lsum, 1);
            lsum += __shfl_xor_sync(0xffffffffu, lsum, 2);

            if (sub == 0) {
                const float a = __expf(mold - mnew);
                sm_a[row] = a;
                sm_m[row] = mnew;
                sm_l[row] = sm_l[row] * a + lsum;
            }
        }
        __syncthreads();

        /* rescale + P@V accumulate. thread -> rows {ty2+8i}, cols tx2*4..+3 */
#pragma unroll
        for (int i = 0; i < 8; i++) {
            const float a = sm_a[ty2 + 8 * i];
            O[i][0] *= a; O[i][1] *= a; O[i][2] *= a; O[i][3] *= a;
        }
        const float4* V4 = (const float4*)Vs;
        for (int j = 0; j < TK; j++) {
            const float4 v = V4[j * 32 + tx2];
#pragma unroll
            for (int i = 0; i < 8; i++) {
                const float pv = Ps[(ty2 + 8 * i) * 65 + j];
                O[i][0] += pv * v.x;
                O[i][1] += pv * v.y;
                O[i][2] += pv * v.z;
                O[i][3] += pv * v.w;
            }
        }
    }
    __syncthreads();

    /* normalize + store */
#pragma unroll
    for (int i = 0; i < 8; i++) {
        const int r = ty2 + 8 * i;
        const int grow = qs + r;
        if (grow < S_TOK) {
            const float inv = 1.f / sm_l[r];
            float4 o = make_float4(O[i][0] * inv, O[i][1] * inv,
                                   O[i][2] * inv, O[i][3] * inv);
            *(float4*)&g_o[(size_t)grow * DIM + h * HD + tx2 * 4] = o;
        }
    }
}

/* ================= launch ================= */
extern "C" void kernel_launch(void* const* d_in, const int* in_sizes, int n_in,
                              void* d_out, int out_size)
{
    const float* x    = (const float*)d_in[0];
    /* d_in[1] seq_lens, d_in[2] grid_sizes: compile-time constants here */
    const float* fcos = (const float*)d_in[3];
    const float* fsin = (const float*)d_in[4];
    const float* Wq = (const float*)d_in[5];  const float* bq = (const float*)d_in[6];
    const float* Wk = (const float*)d_in[7];  const float* bk = (const float*)d_in[8];
    const float* Wv = (const float*)d_in[9];  const float* bv = (const float*)d_in[10];
    const float* Wo = (const float*)d_in[11]; const float* bo = (const float*)d_in[12];
    const float* gq = (const float*)d_in[13]; const float* gk = (const float*)d_in[14];
    float* out = (float*)d_out;

    float *dq, *dk, *dv, *dobuf;
    cudaGetSymbolAddress((void**)&dq,    g_q);
    cudaGetSymbolAddress((void**)&dk,    g_k);
    cudaGetSymbolAddress((void**)&dv,    g_v);
    cudaGetSymbolAddress((void**)&dobuf, g_o);

    const dim3 gemm_grid(DIM / BN, (S_TOK + BM - 1) / BM);   /* (12, 25) */

    gemm_tf32_kernel<<<gemm_grid, 256>>>(x, Wq, bq, dq, S_TOK, DIM, DIM);
    gemm_tf32_kernel<<<gemm_grid, 256>>>(x, Wk, bk, dk, S_TOK, DIM, DIM);
    gemm_tf32_kernel<<<gemm_grid, 256>>>(x, Wv, bv, dv, S_TOK, DIM, DIM);

    rms_rope_kernel<<<dim3(S_TOK, 2), 256>>>(fcos, fsin, gq, gk);

    const int smem_attn = SMEM_ATTN_FLOATS * sizeof(float);   /* ~116 KB */
    cudaFuncSetAttribute(attn_kernel, cudaFuncAttributeMaxDynamicSharedMemorySize, smem_attn);
    attn_kernel<<<dim3((S_TOK + TQ - 1) / TQ, NH), 256, smem_attn>>>();

    gemm_tf32_kernel<<<gemm_grid, 256>>>(dobuf, Wo, bo, out, S_TOK, DIM, DIM);
}

// round 3
// speedup vs baseline: 1.4249x; 1.0914x over previous
#include <cuda_runtime.h>
#include <math.h>
#include <stdint.h>

#define S_TOK 3120
#define DIM   1536
#define NH    12
#define HD    128
#define FRAME 520   /* H*W = 20*26 */
#define TK    64

/* ---- scratch (static device globals; no allocation allowed) ---- */
__device__ float g_q[S_TOK * DIM];
__device__ float g_k[S_TOK * DIM];
__device__ float g_v[S_TOK * DIM];
__device__ float g_o[S_TOK * DIM];

__device__ __forceinline__ uint32_t f2tf32(float x) {
    uint32_t u;
    asm("cvt.rna.tf32.f32 %0, %1;" : "=r"(u) : "f"(x));
    return u;
}
__device__ __forceinline__ float tf32r(float x) { return __uint_as_float(f2tf32(x)); }

__device__ __forceinline__ void mma_tf32(float* c, const uint32_t* a, uint32_t b0, uint32_t b1) {
    asm volatile(
        "mma.sync.aligned.m16n8k8.row.col.f32.tf32.tf32.f32 "
        "{%0,%1,%2,%3}, {%4,%5,%6,%7}, {%8,%9}, {%0,%1,%2,%3};"
        : "+f"(c[0]), "+f"(c[1]), "+f"(c[2]), "+f"(c[3])
        : "r"(a[0]), "r"(a[1]), "r"(a[2]), "r"(a[3]), "r"(b0), "r"(b1));
}

/* ================= tf32 tensor-core GEMM (unchanged from R2) ================= */
#define BM 128
#define BN 128
#define BK 16

__global__ __launch_bounds__(256, 2) void gemm_tf32_kernel(
    const float* __restrict__ A, const float* __restrict__ W,
    const float* __restrict__ bias, float* __restrict__ C,
    int M, int N, int K)
{
    __shared__ float As[BK][BM + 4];
    __shared__ float Bs[BK][BN + 4];

    const int tid  = threadIdx.x;
    const int warp = tid >> 5;
    const int lane = tid & 31;
    const int r    = lane >> 2;
    const int c    = lane & 3;

    const int bm = blockIdx.y * BM;
    const int bn = blockIdx.x * BN;
    const int wm = (warp & 3) * 32;
    const int wn = (warp >> 2) * 64;

    float acc[2][8][4];
#pragma unroll
    for (int mi = 0; mi < 2; mi++)
#pragma unroll
        for (int nj = 0; nj < 8; nj++)
#pragma unroll
            for (int e = 0; e < 4; e++) acc[mi][nj][e] = 0.f;

    const int arow = tid >> 1;
    const int acol = (tid & 1) * 8;
    const int brow = tid >> 4;
    const int bcol = (tid & 15) * 8;

    for (int kt = 0; kt < K; kt += BK) {
        float4 av0, av1;
        if (bm + arow < M) {
            const float* ap = &A[(size_t)(bm + arow) * K + kt + acol];
            av0 = *(const float4*)ap;
            av1 = *(const float4*)(ap + 4);
        } else {
            av0 = make_float4(0.f, 0.f, 0.f, 0.f);
            av1 = av0;
        }
        As[acol + 0][arow] = tf32r(av0.x);
        As[acol + 1][arow] = tf32r(av0.y);
        As[acol + 2][arow] = tf32r(av0.z);
        As[acol + 3][arow] = tf32r(av0.w);
        As[acol + 4][arow] = tf32r(av1.x);
        As[acol + 5][arow] = tf32r(av1.y);
        As[acol + 6][arow] = tf32r(av1.z);
        As[acol + 7][arow] = tf32r(av1.w);

        {
            const float* bp = &W[(size_t)(kt + brow) * N + bn + bcol];
            float4 bv0 = *(const float4*)bp;
            float4 bv1 = *(const float4*)(bp + 4);
            float4 o0 = make_float4(tf32r(bv0.x), tf32r(bv0.y), tf32r(bv0.z), tf32r(bv0.w));
            float4 o1 = make_float4(tf32r(bv1.x), tf32r(bv1.y), tf32r(bv1.z), tf32r(bv1.w));
            *(float4*)&Bs[brow][bcol]     = o0;
            *(float4*)&Bs[brow][bcol + 4] = o1;
        }
        __syncthreads();

#pragma unroll
        for (int kk = 0; kk < BK; kk += 8) {
            uint32_t af[2][4];
#pragma unroll
            for (int mi = 0; mi < 2; mi++) {
                const int m0 = wm + mi * 16;
                af[mi][0] = __float_as_uint(As[kk + c][m0 + r]);
                af[mi][1] = __float_as_uint(As[kk + c][m0 + r + 8]);
                af[mi][2] = __float_as_uint(As[kk + c + 4][m0 + r]);
                af[mi][3] = __float_as_uint(As[kk + c + 4][m0 + r + 8]);
            }
            uint32_t bf[8][2];
#pragma unroll
            for (int nj = 0; nj < 8; nj++) {
                const int n0 = wn + nj * 8;
                bf[nj][0] = __float_as_uint(Bs[kk + c][n0 + r]);
                bf[nj][1] = __float_as_uint(Bs[kk + c + 4][n0 + r]);
            }
#pragma unroll
            for (int mi = 0; mi < 2; mi++)
#pragma unroll
                for (int nj = 0; nj < 8; nj++)
                    mma_tf32(acc[mi][nj], af[mi], bf[nj][0], bf[nj][1]);
        }
        __syncthreads();
    }

#pragma unroll
    for (int mi = 0; mi < 2; mi++) {
        const int row0 = bm + wm + mi * 16 + r;
        const int row1 = row0 + 8;
#pragma unroll
        for (int nj = 0; nj < 8; nj++) {
            const int col = bn + wn + nj * 8 + 2 * c;
            const float b0 = bias[col];
            const float b1 = bias[col + 1];
            if (row0 < M) {
                float2 o = make_float2(acc[mi][nj][0] + b0, acc[mi][nj][1] + b1);
                *(float2*)&C[(size_t)row0 * N + col] = o;
            }
            if (row1 < M) {
                float2 o = make_float2(acc[mi][nj][2] + b0, acc[mi][nj][3] + b1);
                *(float2*)&C[(size_t)row1 * N + col] = o;
            }
        }
    }
}

/* ============ fused RMSNorm + 3-axis RoPE, in place (unchanged) ============ */
__global__ __launch_bounds__(256) void rms_rope_kernel(
    const float* __restrict__ fcos, const float* __restrict__ fsin,
    const float* __restrict__ gq, const float* __restrict__ gk)
{
    const int row   = blockIdx.x;
    const int which = blockIdx.y;
    float* buf      = which ? g_k : g_q;
    const float* g  = which ? gk : gq;
    const int tid   = threadIdx.x;

    const float* p = buf + (size_t)row * DIM;
    float ss = 0.f;
    for (int i = tid; i < DIM; i += 256) { float v = p[i]; ss += v * v; }

    __shared__ float red[256];
    red[tid] = ss;
    __syncthreads();
    for (int s = 128; s > 0; s >>= 1) {
        if (tid < s) red[tid] += red[tid + s];
        __syncthreads();
    }
    const float inv = rsqrtf(red[0] * (1.0f / DIM) + 1e-6f);

    const int f  = row / FRAME;
    const int hh = (row / 26) % 20;
    const int ww = row % 26;

    for (int pi = tid; pi < NH * 64; pi += 256) {
        const int head = pi >> 6;
        const int c    = pi & 63;
        const int pr   = (c < 22) ? f : ((c < 43) ? hh : ww);
        const float cs = fcos[pr * 64 + c];
        const float sn = fsin[pr * 64 + c];
        const size_t base = (size_t)row * DIM + head * HD + 2 * c;
        const float xr = buf[base]     * inv * g[head * HD + 2 * c];
        const float xi = buf[base + 1] * inv * g[head * HD + 2 * c + 1];
        buf[base]     = xr * cs - xi * sn;
        buf[base + 1] = xr * sn + xi * cs;
    }
}

/* ========== tensor-core flash attention (tf32, compensated QK) ========== */
#define AQ_PAD 132
#define AV_PAD 69
#define AP_PAD 68
#define ATTN_SMEM_FLOATS (4 * 64 * AQ_PAD + 128 * AV_PAD + 64 * AP_PAD)

__global__ __launch_bounds__(128) void attn_mma_kernel()
{
    extern __shared__ float sm[];
    float* Qh = sm;
    float* Ql = Qh + 64 * AQ_PAD;
    float* Kh = Ql + 64 * AQ_PAD;
    float* Kl = Kh + 64 * AQ_PAD;
    float* Vt = Kl + 64 * AQ_PAD;     /* [128][AV_PAD], transposed */
    float* Ps = Vt + 128 * AV_PAD;    /* [64][AP_PAD] */

    const int tid  = threadIdx.x;
    const int warp = tid >> 5;
    const int lane = tid & 31;
    const int gr   = lane >> 2;   /* 0..7 */
    const int gc   = lane & 3;    /* 0..3 */
    const int qs   = blockIdx.x * 64;
    const int h    = blockIdx.y;

    /* load Q tile: hi/lo tf32 split */
    {
        const int r  = tid >> 1;
        const int c0 = (tid & 1) * 64;
        const bool valid = (qs + r) < S_TOK;
        const float* src = &g_q[(size_t)(qs + r) * DIM + h * HD + c0];
#pragma unroll
        for (int i = 0; i < 16; i++) {
            float4 x = valid ? *(const float4*)(src + i * 4) : make_float4(0.f, 0.f, 0.f, 0.f);
            float h0 = tf32r(x.x), h1 = tf32r(x.y), h2 = tf32r(x.z), h3 = tf32r(x.w);
            *(float4*)&Qh[r * AQ_PAD + c0 + i * 4] = make_float4(h0, h1, h2, h3);
            *(float4*)&Ql[r * AQ_PAD + c0 + i * 4] =
                make_float4(tf32r(x.x - h0), tf32r(x.y - h1), tf32r(x.z - h2), tf32r(x.w - h3));
        }
    }

    const int row_l0 = warp * 16 + gr;        /* local row in [0,64) */
    const int row_l1 = row_l0 + 8;
    const int fi0 = (qs + row_l0) / FRAME;
    const int fi1 = (qs + row_l1) / FRAME;

    float m0 = -1e30f, m1 = -1e30f, l0 = 0.f, l1 = 0.f;
    float O[16][4];
#pragma unroll
    for (int nt = 0; nt < 16; nt++)
#pragma unroll
        for (int e = 0; e < 4; e++) O[nt][e] = 0.f;

    /* key-range setup (sink frame 0 + local window) */
    const int fi_min = qs / FRAME;
    const int fi_max = min(qs + 63, S_TOK - 1) / FRAME;
    int lo = fi_min - 3; if (lo < 0) lo = 0;
    lo *= FRAME;
    int hi = (fi_max + 1) * FRAME; if (hi > S_TOK) hi = S_TOK;
    int starts[2], ends[2], nr;
    if (lo <= FRAME) { nr = 1; starts[0] = 0; ends[0] = hi; }
    else { nr = 2; starts[0] = 0; ends[0] = FRAME; starts[1] = (lo / TK) * TK; ends[1] = hi; }

    const float scale = 0.08838834764831845f;

    for (int rr = 0; rr < nr; rr++)
    for (int ks = starts[rr]; ks < ends[rr]; ks += TK) {
        __syncthreads();

        /* K tile: hi/lo split */
        {
            const int r  = tid >> 1;
            const int c0 = (tid & 1) * 64;
            const bool valid = (ks + r) < S_TOK;
            const float* src = &g_k[(size_t)(ks + r) * DIM + h * HD + c0];
#pragma unroll
            for (int i = 0; i < 16; i++) {
                float4 x = valid ? *(const float4*)(src + i * 4) : make_float4(0.f, 0.f, 0.f, 0.f);
                float h0 = tf32r(x.x), h1 = tf32r(x.y), h2 = tf32r(x.z), h3 = tf32r(x.w);
                *(float4*)&Kh[r * AQ_PAD + c0 + i * 4] = make_float4(h0, h1, h2, h3);
                *(float4*)&Kl[r * AQ_PAD + c0 + i * 4] =
                    make_float4(tf32r(x.x - h0), tf32r(x.y - h1), tf32r(x.z - h2), tf32r(x.w - h3));
            }
        }
        /* V tile, transposed: Vt[d][r] */
        {
#pragma unroll 4
            for (int rr2 = 0; rr2 < 16; rr2++) {
                const int r = warp * 16 + rr2;
                const bool valid = (ks + r) < S_TOK;
                const float* src = &g_v[(size_t)(ks + r) * DIM + h * HD];
#pragma unroll
                for (int d0 = 0; d0 < 128; d0 += 32) {
                    float x = valid ? src[d0 + lane] : 0.f;
                    Vt[(d0 + lane) * AV_PAD + r] = tf32r(x);
                }
            }
        }
        __syncthreads();

        /* ---- QK^T (3-term compensated tf32) ---- */
        float Sa[8][4];
#pragma unroll
        for (int nj = 0; nj < 8; nj++)
#pragma unroll
            for (int e = 0; e < 4; e++) Sa[nj][e] = 0.f;

#pragma unroll
        for (int kc = 0; kc < 16; kc++) {
            const int k0 = kc * 8 + gc;
            uint32_t ah[4], al[4];
            ah[0] = __float_as_uint(Qh[row_l0 * AQ_PAD + k0]);
            ah[1] = __float_as_uint(Qh[row_l1 * AQ_PAD + k0]);
            ah[2] = __float_as_uint(Qh[row_l0 * AQ_PAD + k0 + 4]);
            ah[3] = __float_as_uint(Qh[row_l1 * AQ_PAD + k0 + 4]);
            al[0] = __float_as_uint(Ql[row_l0 * AQ_PAD + k0]);
            al[1] = __float_as_uint(Ql[row_l1 * AQ_PAD + k0]);
            al[2] = __float_as_uint(Ql[row_l0 * AQ_PAD + k0 + 4]);
            al[3] = __float_as_uint(Ql[row_l1 * AQ_PAD + k0 + 4]);
#pragma unroll
            for (int nj = 0; nj < 8; nj++) {
                const int n = nj * 8 + gr;
                uint32_t bh0 = __float_as_uint(Kh[n * AQ_PAD + k0]);
                uint32_t bh1 = __float_as_uint(Kh[n * AQ_PAD + k0 + 4]);
                uint32_t bl0 = __float_as_uint(Kl[n * AQ_PAD + k0]);
                uint32_t bl1 = __float_as_uint(Kl[n * AQ_PAD + k0 + 4]);
                mma_tf32(Sa[nj], ah, bh0, bh1);
                mma_tf32(Sa[nj], al, bh0, bh1);
                mma_tf32(Sa[nj], ah, bl0, bl1);
            }
        }

        /* ---- scale + frame mask ---- */
        float mloc0 = -1e30f, mloc1 = -1e30f;
#pragma unroll
        for (int nj = 0; nj < 8; nj++) {
            const int cg = ks + nj * 8 + 2 * gc;     /* even; pair never straddles a frame */
            const int fj = cg / FRAME;
            const bool kv = (cg < S_TOK);
            const bool ok0 = kv && (fj <= fi0) && (((fi0 - fj) < 4) || (fj == 0));
            const bool ok1 = kv && (fj <= fi1) && (((fi1 - fj) < 4) || (fj == 0));
            Sa[nj][0] = ok0 ? Sa[nj][0] * scale : -1e30f;
            Sa[nj][1] = ok0 ? Sa[nj][1] * scale : -1e30f;
            Sa[nj][2] = ok1 ? Sa[nj][2] * scale : -1e30f;
            Sa[nj][3] = ok1 ? Sa[nj][3] * scale : -1e30f;
            mloc0 = fmaxf(mloc0, fmaxf(Sa[nj][0], Sa[nj][1]));
            mloc1 = fmaxf(mloc1, fmaxf(Sa[nj][2], Sa[nj][3]));
        }
        mloc0 = fmaxf(mloc0, __shfl_xor_sync(0xffffffffu, mloc0, 1));
        mloc0 = fmaxf(mloc0, __shfl_xor_sync(0xffffffffu, mloc0, 2));
        mloc1 = fmaxf(mloc1, __shfl_xor_sync(0xffffffffu, mloc1, 1));
        mloc1 = fmaxf(mloc1, __shfl_xor_sync(0xffffffffu, mloc1, 2));

        const float mn0 = fmaxf(m0, mloc0);
        const float mn1 = fmaxf(m1, mloc1);
        const float a0 = __expf(m0 - mn0);
        const float a1 = __expf(m1 - mn1);
        m0 = mn0; m1 = mn1;

        /* exp + write P to shared (tf32) + row sums */
        float ls0 = 0.f, ls1 = 0.f;
#pragma unroll
        for (int nj = 0; nj < 8; nj++) {
            const int cc = nj * 8 + 2 * gc;
            float p00 = __expf(Sa[nj][0] - mn0);
            float p01 = __expf(Sa[nj][1] - mn0);
            float p10 = __expf(Sa[nj][2] - mn1);
            float p11 = __expf(Sa[nj][3] - mn1);
            ls0 += p00 + p01;
            ls1 += p10 + p11;
            Ps[row_l0 * AP_PAD + cc]     = tf32r(p00);
            Ps[row_l0 * AP_PAD + cc + 1] = tf32r(p01);
            Ps[row_l1 * AP_PAD + cc]     = tf32r(p10);
            Ps[row_l1 * AP_PAD + cc + 1] = tf32r(p11);
        }
        ls0 += __shfl_xor_sync(0xffffffffu, ls0, 1);
        ls0 += __shfl_xor_sync(0xffffffffu, ls0, 2);
        ls1 += __shfl_xor_sync(0xffffffffu, ls1, 1);
        ls1 += __shfl_xor_sync(0xffffffffu, ls1, 2);
        l0 = l0 * a0 + ls0;
        l1 = l1 * a1 + ls1;

        /* rescale O */
#pragma unroll
        for (int nt = 0; nt < 16; nt++) {
            O[nt][0] *= a0; O[nt][1] *= a0;
            O[nt][2] *= a1; O[nt][3] *= a1;
        }
        __syncwarp();

        /* ---- P @ V ---- */
#pragma unroll
        for (int kc = 0; kc < 8; kc++) {
            const int k0 = kc * 8 + gc;
            uint32_t pa[4];
            pa[0] = __float_as_uint(Ps[row_l0 * AP_PAD + k0]);
            pa[1] = __float_as_uint(Ps[row_l1 * AP_PAD + k0]);
            pa[2] = __float_as_uint(Ps[row_l0 * AP_PAD + k0 + 4]);
            pa[3] = __float_as_uint(Ps[row_l1 * AP_PAD + k0 + 4]);
#pragma unroll
            for (int nt = 0; nt < 16; nt++) {
                const int d = nt * 8 + gr;
                uint32_t b0 = __float_as_uint(Vt[d * AV_PAD + k0]);
                uint32_t b1 = __float_as_uint(Vt[d * AV_PAD + k0 + 4]);
                mma_tf32(O[nt], pa, b0, b1);
            }
        }
    }

    /* normalize + store */
    const float inv0 = 1.f / l0;
    const float inv1 = 1.f / l1;
    const int rg0 = qs + row_l0;
    const int rg1 = qs + row_l1;
#pragma unroll
    for (int nt = 0; nt < 16; nt++) {
        const int col = h * HD + nt * 8 + 2 * gc;
        if (rg0 < S_TOK)
            *(float2*)&g_o[(size_t)rg0 * DIM + col] = make_float2(O[nt][0] * inv0, O[nt][1] * inv0);
        if (rg1 < S_TOK)
            *(float2*)&g_o[(size_t)rg1 * DIM + col] = make_float2(O[nt][2] * inv1, O[nt][3] * inv1);
    }
}

/* ================= launch ================= */
extern "C" void kernel_launch(void* const* d_in, const int* in_sizes, int n_in,
                              void* d_out, int out_size)
{
    const float* x    = (const float*)d_in[0];
    const float* fcos = (const float*)d_in[3];
    const float* fsin = (const float*)d_in[4];
    const float* Wq = (const float*)d_in[5];  const float* bq = (const float*)d_in[6];
    const float* Wk = (const float*)d_in[7];  const float* bk = (const float*)d_in[8];
    const float* Wv = (const float*)d_in[9];  const float* bv = (const float*)d_in[10];
    const float* Wo = (const float*)d_in[11]; const float* bo = (const float*)d_in[12];
    const float* gq = (const float*)d_in[13]; const float* gk = (const float*)d_in[14];
    float* out = (float*)d_out;

    float *dq, *dk, *dv, *dobuf;
    cudaGetSymbolAddress((void**)&dq,    g_q);
    cudaGetSymbolAddress((void**)&dk,    g_k);
    cudaGetSymbolAddress((void**)&dv,    g_v);
    cudaGetSymbolAddress((void**)&dobuf, g_o);

    const dim3 gemm_grid(DIM / BN, (S_TOK + BM - 1) / BM);

    gemm_tf32_kernel<<<gemm_grid, 256>>>(x, Wq, bq, dq, S_TOK, DIM, DIM);
    gemm_tf32_kernel<<<gemm_grid, 256>>>(x, Wk, bk, dk, S_TOK, DIM, DIM);
    gemm_tf32_kernel<<<gemm_grid, 256>>>(x, Wv, bv, dv, S_TOK, DIM, DIM);

    rms_rope_kernel<<<dim3(S_TOK, 2), 256>>>(fcos, fsin, gq, gk);

    const int smem_attn = ATTN_SMEM_FLOATS * sizeof(float);   /* ~188 KB */
    cudaFuncSetAttribute(attn_mma_kernel, cudaFuncAttributeMaxDynamicSharedMemorySize, smem_attn);
    attn_mma_kernel<<<dim3((S_TOK + 63) / 64, NH), 128, smem_attn>>>();

    gemm_tf32_kernel<<<gemm_grid, 256>>>(dobuf, Wo, bo, out, S_TOK, DIM, DIM);
}

// round 4
// speedup vs baseline: 1.6486x; 1.1570x over previous
#include <cuda_runtime.h>
#include <math.h>
#include <stdint.h>

#define S_TOK 3120
#define DIM   1536
#define NH    12
#define HD    128
#define FRAME 520   /* H*W = 20*26 */
#define TK    64

/* ---- scratch (static device globals; no allocation allowed) ---- */
__device__ float g_q[S_TOK * DIM];
__device__ float g_k[S_TOK * DIM];
__device__ float g_v[S_TOK * DIM];
__device__ float g_o[S_TOK * DIM];

__device__ __forceinline__ uint32_t f2tf32(float x) {
    uint32_t u;
    asm("cvt.rna.tf32.f32 %0, %1;" : "=r"(u) : "f"(x));
    return u;
}
__device__ __forceinline__ float tf32r(float x) { return __uint_as_float(f2tf32(x)); }

__device__ __forceinline__ void mma_tf32(float* c, const uint32_t* a, uint32_t b0, uint32_t b1) {
    asm volatile(
        "mma.sync.aligned.m16n8k8.row.col.f32.tf32.tf32.f32 "
        "{%0,%1,%2,%3}, {%4,%5,%6,%7}, {%8,%9}, {%0,%1,%2,%3};"
        : "+f"(c[0]), "+f"(c[1]), "+f"(c[2]), "+f"(c[3])
        : "r"(a[0]), "r"(a[1]), "r"(a[2]), "r"(a[3]), "r"(b0), "r"(b1));
}

__device__ __forceinline__ void cp_async16(void* smem_dst, const void* gsrc, bool valid) {
    uint32_t saddr = (uint32_t)__cvta_generic_to_shared(smem_dst);
    int sz = valid ? 16 : 0;
    asm volatile("cp.async.cg.shared.global [%0], [%1], 16, %2;\n"
                 :: "r"(saddr), "l"(gsrc), "r"(sz));
}
__device__ __forceinline__ void cp_commit() {
    asm volatile("cp.async.commit_group;\n");
}
template <int N>
__device__ __forceinline__ void cp_wait() {
    asm volatile("cp.async.wait_group %0;\n" :: "n"(N));
}

/* ================= tf32 tensor-core GEMM, cp.async 2-stage pipeline ================= */
#define BM 128
#define BN 128
#define BK 16
#define AS_STRIDE 20    /* conflict-free: banks 20r+c all distinct */
#define BS_STRIDE 136   /* conflict-free: banks 8c+r all distinct  */

__global__ __launch_bounds__(256, 2) void gemm_tf32_kernel(
    const float* __restrict__ A, const float* __restrict__ W,
    const float* __restrict__ bias, float* __restrict__ C,
    int M, int N, int K)
{
    __shared__ float As[2][BM][AS_STRIDE];   /* raw fp32; [m][k] */
    __shared__ float Bs[2][BK][BS_STRIDE];   /* raw fp32; [k][n] */

    const int tid  = threadIdx.x;
    const int warp = tid >> 5;
    const int lane = tid & 31;
    const int r    = lane >> 2;
    const int c    = lane & 3;

    const int bm = blockIdx.y * BM;
    const int bn = blockIdx.x * BN;
    const int wm = (warp & 3) * 32;
    const int wn = (warp >> 2) * 64;

    /* copy index precompute (2 chunks of 16B per array per thread) */
    const int a_row0 = tid >> 2;              /* chunks 0..255   */
    const int a_cs0  = (tid & 3) * 4;
    const int a_row1 = (tid + 256) >> 2;      /* chunks 256..511 */
    const int a_cs1  = a_cs0;                 /* (ch&3) identical */
    const int b_row0 = tid >> 5;
    const int b_cs0  = (tid & 31) * 4;
    const int b_row1 = (tid + 256) >> 5;
    const int b_cs1  = b_cs0;

    const bool a_v0 = (bm + a_row0) < M;
    const bool a_v1 = (bm + a_row1) < M;

    float acc[2][8][4];
#pragma unroll
    for (int mi = 0; mi < 2; mi++)
#pragma unroll
        for (int nj = 0; nj < 8; nj++)
#pragma unroll
            for (int e = 0; e < 4; e++) acc[mi][nj][e] = 0.f;

    const int NT = K / BK;   /* 96 */

    /* prefetch stage 0 */
    {
        const int kt = 0;
        cp_async16(&As[0][a_row0][a_cs0], &A[(size_t)(bm + a_row0) * K + kt + a_cs0], a_v0);
        cp_async16(&As[0][a_row1][a_cs1], &A[(size_t)(bm + a_row1) * K + kt + a_cs1], a_v1);
        cp_async16(&Bs[0][b_row0][b_cs0], &W[(size_t)(kt + b_row0) * N + bn + b_cs0], true);
        cp_async16(&Bs[0][b_row1][b_cs1], &W[(size_t)(kt + b_row1) * N + bn + b_cs1], true);
    }
    cp_commit();

    for (int t = 0; t < NT; t++) {
        /* issue stage t+1 while t is in flight / being computed */
        if (t + 1 < NT) {
            const int kt = (t + 1) * BK;
            const int s  = (t + 1) & 1;
            cp_async16(&As[s][a_row0][a_cs0], &A[(size_t)(bm + a_row0) * K + kt + a_cs0], a_v0);
            cp_async16(&As[s][a_row1][a_cs1], &A[(size_t)(bm + a_row1) * K + kt + a_cs1], a_v1);
            cp_async16(&Bs[s][b_row0][b_cs0], &W[(size_t)(kt + b_row0) * N + bn + b_cs0], true);
            cp_async16(&Bs[s][b_row1][b_cs1], &W[(size_t)(kt + b_row1) * N + bn + b_cs1], true);
        }
        cp_commit();
        cp_wait<1>();          /* stage t complete; stage t+1 may be pending */
        __syncthreads();

        const int b = t & 1;
#pragma unroll
        for (int kk = 0; kk < BK; kk += 8) {
            uint32_t af[2][4];
#pragma unroll
            for (int mi = 0; mi < 2; mi++) {
                const int m0 = wm + mi * 16;
                af[mi][0] = f2tf32(As[b][m0 + r]    [kk + c]);
                af[mi][1] = f2tf32(As[b][m0 + r + 8][kk + c]);
                af[mi][2] = f2tf32(As[b][m0 + r]    [kk + c + 4]);
                af[mi][3] = f2tf32(As[b][m0 + r + 8][kk + c + 4]);
            }
            uint32_t bf[8][2];
#pragma unroll
            for (int nj = 0; nj < 8; nj++) {
                const int n0 = wn + nj * 8;
                bf[nj][0] = f2tf32(Bs[b][kk + c]    [n0 + r]);
                bf[nj][1] = f2tf32(Bs[b][kk + c + 4][n0 + r]);
            }
#pragma unroll
            for (int mi = 0; mi < 2; mi++)
#pragma unroll
                for (int nj = 0; nj < 8; nj++)
                    mma_tf32(acc[mi][nj], af[mi], bf[nj][0], bf[nj][1]);
        }
        __syncthreads();   /* compute(t) done before stage t+2 overwrites buf b */
    }

    /* ---- epilogue: bias + store ---- */
#pragma unroll
    for (int mi = 0; mi < 2; mi++) {
        const int row0 = bm + wm + mi * 16 + r;
        const int row1 = row0 + 8;
#pragma unroll
        for (int nj = 0; nj < 8; nj++) {
            const int col = bn + wn + nj * 8 + 2 * c;
            const float b0 = bias[col];
            const float b1 = bias[col + 1];
            if (row0 < M) {
                float2 o = make_float2(acc[mi][nj][0] + b0, acc[mi][nj][1] + b1);
                *(float2*)&C[(size_t)row0 * N + col] = o;
            }
            if (row1 < M) {
                float2 o = make_float2(acc[mi][nj][2] + b0, acc[mi][nj][3] + b1);
                *(float2*)&C[(size_t)row1 * N + col] = o;
            }
        }
    }
}

/* ============ fused RMSNorm + 3-axis RoPE, in place (unchanged) ============ */
__global__ __launch_bounds__(256) void rms_rope_kernel(
    const float* __restrict__ fcos, const float* __restrict__ fsin,
    const float* __restrict__ gq, const float* __restrict__ gk)
{
    const int row   = blockIdx.x;
    const int which = blockIdx.y;
    float* buf      = which ? g_k : g_q;
    const float* g  = which ? gk : gq;
    const int tid   = threadIdx.x;

    const float* p = buf + (size_t)row * DIM;
    float ss = 0.f;
    for (int i = tid; i < DIM; i += 256) { float v = p[i]; ss += v * v; }

    __shared__ float red[256];
    red[tid] = ss;
    __syncthreads();
    for (int s = 128; s > 0; s >>= 1) {
        if (tid < s) red[tid] += red[tid + s];
        __syncthreads();
    }
    const float inv = rsqrtf(red[0] * (1.0f / DIM) + 1e-6f);

    const int f  = row / FRAME;
    const int hh = (row / 26) % 20;
    const int ww = row % 26;

    for (int pi = tid; pi < NH * 64; pi += 256) {
        const int head = pi >> 6;
        const int c    = pi & 63;
        const int pr   = (c < 22) ? f : ((c < 43) ? hh : ww);
        const float cs = fcos[pr * 64 + c];
        const float sn = fsin[pr * 64 + c];
        const size_t base = (size_t)row * DIM + head * HD + 2 * c;
        const float xr = buf[base]     * inv * g[head * HD + 2 * c];
        const float xi = buf[base + 1] * inv * g[head * HD + 2 * c + 1];
        buf[base]     = xr * cs - xi * sn;
        buf[base + 1] = xr * sn + xi * cs;
    }
}

/* ========== tensor-core flash attention (tf32, compensated QK; unchanged) ========== */
#define AQ_PAD 132
#define AV_PAD 69
#define AP_PAD 68
#define ATTN_SMEM_FLOATS (4 * 64 * AQ_PAD + 128 * AV_PAD + 64 * AP_PAD)

__global__ __launch_bounds__(128) void attn_mma_kernel()
{
    extern __shared__ float sm[];
    float* Qh = sm;
    float* Ql = Qh + 64 * AQ_PAD;
    float* Kh = Ql + 64 * AQ_PAD;
    float* Kl = Kh + 64 * AQ_PAD;
    float* Vt = Kl + 64 * AQ_PAD;     /* [128][AV_PAD], transposed */
    float* Ps = Vt + 128 * AV_PAD;    /* [64][AP_PAD] */

    const int tid  = threadIdx.x;
    const int warp = tid >> 5;
    const int lane = tid & 31;
    const int gr   = lane >> 2;
    const int gc   = lane & 3;
    const int qs   = blockIdx.x * 64;
    const int h    = blockIdx.y;

    {
        const int r  = tid >> 1;
        const int c0 = (tid & 1) * 64;
        const bool valid = (qs + r) < S_TOK;
        const float* src = &g_q[(size_t)(qs + r) * DIM + h * HD + c0];
#pragma unroll
        for (int i = 0; i < 16; i++) {
            float4 x = valid ? *(const float4*)(src + i * 4) : make_float4(0.f, 0.f, 0.f, 0.f);
            float h0 = tf32r(x.x), h1 = tf32r(x.y), h2 = tf32r(x.z), h3 = tf32r(x.w);
            *(float4*)&Qh[r * AQ_PAD + c0 + i * 4] = make_float4(h0, h1, h2, h3);
            *(float4*)&Ql[r * AQ_PAD + c0 + i * 4] =
                make_float4(tf32r(x.x - h0), tf32r(x.y - h1), tf32r(x.z - h2), tf32r(x.w - h3));
        }
    }

    const int row_l0 = warp * 16 + gr;
    const int row_l1 = row_l0 + 8;
    const int fi0 = (qs + row_l0) / FRAME;
    const int fi1 = (qs + row_l1) / FRAME;

    float m0 = -1e30f, m1 = -1e30f, l0 = 0.f, l1 = 0.f;
    float O[16][4];
#pragma unroll
    for (int nt = 0; nt < 16; nt++)
#pragma unroll
        for (int e = 0; e < 4; e++) O[nt][e] = 0.f;

    const int fi_min = qs / FRAME;
    const int fi_max = min(qs + 63, S_TOK - 1) / FRAME;
    int lo = fi_min - 3; if (lo < 0) lo = 0;
    lo *= FRAME;
    int hi = (fi_max + 1) * FRAME; if (hi > S_TOK) hi = S_TOK;
    int starts[2], ends[2], nr;
    if (lo <= FRAME) { nr = 1; starts[0] = 0; ends[0] = hi; }
    else { nr = 2; starts[0] = 0; ends[0] = FRAME; starts[1] = (lo / TK) * TK; ends[1] = hi; }

    const float scale = 0.08838834764831845f;

    for (int rr = 0; rr < nr; rr++)
    for (int ks = starts[rr]; ks < ends[rr]; ks += TK) {
        __syncthreads();

        {
            const int r  = tid >> 1;
            const int c0 = (tid & 1) * 64;
            const bool valid = (ks + r) < S_TOK;
            const float* src = &g_k[(size_t)(ks + r) * DIM + h * HD + c0];
#pragma unroll
            for (int i = 0; i < 16; i++) {
                float4 x = valid ? *(const float4*)(src + i * 4) : make_float4(0.f, 0.f, 0.f, 0.f);
                float h0 = tf32r(x.x), h1 = tf32r(x.y), h2 = tf32r(x.z), h3 = tf32r(x.w);
                *(float4*)&Kh[r * AQ_PAD + c0 + i * 4] = make_float4(h0, h1, h2, h3);
                *(float4*)&Kl[r * AQ_PAD + c0 + i * 4] =
                    make_float4(tf32r(x.x - h0), tf32r(x.y - h1), tf32r(x.z - h2), tf32r(x.w - h3));
            }
        }
        {
#pragma unroll 4
            for (int rr2 = 0; rr2 < 16; rr2++) {
                const int r = warp * 16 + rr2;
                const bool valid = (ks + r) < S_TOK;
                const float* src = &g_v[(size_t)(ks + r) * DIM + h * HD];
#pragma unroll
                for (int d0 = 0; d0 < 128; d0 += 32) {
                    float x = valid ? src[d0 + lane] : 0.f;
                    Vt[(d0 + lane) * AV_PAD + r] = tf32r(x);
                }
            }
        }
        __syncthreads();

        float Sa[8][4];
#pragma unroll
        for (int nj = 0; nj < 8; nj++)
#pragma unroll
            for (int e = 0; e < 4; e++) Sa[nj][e] = 0.f;

#pragma unroll
        for (int kc = 0; kc < 16; kc++) {
            const int k0 = kc * 8 + gc;
            uint32_t ah[4], al[4];
            ah[0] = __float_as_uint(Qh[row_l0 * AQ_PAD + k0]);
            ah[1] = __float_as_uint(Qh[row_l1 * AQ_PAD + k0]);
            ah[2] = __float_as_uint(Qh[row_l0 * AQ_PAD + k0 + 4]);
            ah[3] = __float_as_uint(Qh[row_l1 * AQ_PAD + k0 + 4]);
            al[0] = __float_as_uint(Ql[row_l0 * AQ_PAD + k0]);
            al[1] = __float_as_uint(Ql[row_l1 * AQ_PAD + k0]);
            al[2] = __float_as_uint(Ql[row_l0 * AQ_PAD + k0 + 4]);
            al[3] = __float_as_uint(Ql[row_l1 * AQ_PAD + k0 + 4]);
#pragma unroll
            for (int nj = 0; nj < 8; nj++) {
                const int n = nj * 8 + gr;
                uint32_t bh0 = __float_as_uint(Kh[n * AQ_PAD + k0]);
                uint32_t bh1 = __float_as_uint(Kh[n * AQ_PAD + k0 + 4]);
                uint32_t bl0 = __float_as_uint(Kl[n * AQ_PAD + k0]);
                uint32_t bl1 = __float_as_uint(Kl[n * AQ_PAD + k0 + 4]);
                mma_tf32(Sa[nj], ah, bh0, bh1);
                mma_tf32(Sa[nj], al, bh0, bh1);
                mma_tf32(Sa[nj], ah, bl0, bl1);
            }
        }

        float mloc0 = -1e30f, mloc1 = -1e30f;
#pragma unroll
        for (int nj = 0; nj < 8; nj++) {
            const int cg = ks + nj * 8 + 2 * gc;
            const int fj = cg / FRAME;
            const bool kv = (cg < S_TOK);
            const bool ok0 = kv && (fj <= fi0) && (((fi0 - fj) < 4) || (fj == 0));
            const bool ok1 = kv && (fj <= fi1) && (((fi1 - fj) < 4) || (fj == 0));
            Sa[nj][0] = ok0 ? Sa[nj][0] * scale : -1e30f;
            Sa[nj][1] = ok0 ? Sa[nj][1] * scale : -1e30f;
            Sa[nj][2] = ok1 ? Sa[nj][2] * scale : -1e30f;
            Sa[nj][3] = ok1 ? Sa[nj][3] * scale : -1e30f;
            mloc0 = fmaxf(mloc0, fmaxf(Sa[nj][0], Sa[nj][1]));
            mloc1 = fmaxf(mloc1, fmaxf(Sa[nj][2], Sa[nj][3]));
        }
        mloc0 = fmaxf(mloc0, __shfl_xor_sync(0xffffffffu, mloc0, 1));
        mloc0 = fmaxf(mloc0, __shfl_xor_sync(0xffffffffu, mloc0, 2));
        mloc1 = fmaxf(mloc1, __shfl_xor_sync(0xffffffffu, mloc1, 1));
        mloc1 = fmaxf(mloc1, __shfl_xor_sync(0xffffffffu, mloc1, 2));

        const float mn0 = fmaxf(m0, mloc0);
        const float mn1 = fmaxf(m1, mloc1);
        const float a0 = __expf(m0 - mn0);
        const float a1 = __expf(m1 - mn1);
        m0 = mn0; m1 = mn1;

        float ls0 = 0.f, ls1 = 0.f;
#pragma unroll
        for (int nj = 0; nj < 8; nj++) {
            const int cc = nj * 8 + 2 * gc;
            float p00 = __expf(Sa[nj][0] - mn0);
            float p01 = __expf(Sa[nj][1] - mn0);
            float p10 = __expf(Sa[nj][2] - mn1);
            float p11 = __expf(Sa[nj][3] - mn1);
            ls0 += p00 + p01;
            ls1 += p10 + p11;
            Ps[row_l0 * AP_PAD + cc]     = tf32r(p00);
            Ps[row_l0 * AP_PAD + cc + 1] = tf32r(p01);
            Ps[row_l1 * AP_PAD + cc]     = tf32r(p10);
            Ps[row_l1 * AP_PAD + cc + 1] = tf32r(p11);
        }
        ls0 += __shfl_xor_sync(0xffffffffu, ls0, 1);
        ls0 += __shfl_xor_sync(0xffffffffu, ls0, 2);
        ls1 += __shfl_xor_sync(0xffffffffu, ls1, 1);
        ls1 += __shfl_xor_sync(0xffffffffu, ls1, 2);
        l0 = l0 * a0 + ls0;
        l1 = l1 * a1 + ls1;

#pragma unroll
        for (int nt = 0; nt < 16; nt++) {
            O[nt][0] *= a0; O[nt][1] *= a0;
            O[nt][2] *= a1; O[nt][3] *= a1;
        }
        __syncwarp();

#pragma unroll
        for (int kc = 0; kc < 8; kc++) {
            const int k0 = kc * 8 + gc;
            uint32_t pa[4];
            pa[0] = __float_as_uint(Ps[row_l0 * AP_PAD + k0]);
            pa[1] = __float_as_uint(Ps[row_l1 * AP_PAD + k0]);
            pa[2] = __float_as_uint(Ps[row_l0 * AP_PAD + k0 + 4]);
            pa[3] = __float_as_uint(Ps[row_l1 * AP_PAD + k0 + 4]);
#pragma unroll
            for (int nt = 0; nt < 16; nt++) {
                const int d = nt * 8 + gr;
                uint32_t b0 = __float_as_uint(Vt[d * AV_PAD + k0]);
                uint32_t b1 = __float_as_uint(Vt[d * AV_PAD + k0 + 4]);
                mma_tf32(O[nt], pa, b0, b1);
            }
        }
    }

    const float inv0 = 1.f / l0;
    const float inv1 = 1.f / l1;
    const int rg0 = qs + row_l0;
    const int rg1 = qs + row_l1;
#pragma unroll
    for (int nt = 0; nt < 16; nt++) {
        const int col = h * HD + nt * 8 + 2 * gc;
        if (rg0 < S_TOK)
            *(float2*)&g_o[(size_t)rg0 * DIM + col] = make_float2(O[nt][0] * inv0, O[nt][1] * inv0);
        if (rg1 < S_TOK)
            *(float2*)&g_o[(size_t)rg1 * DIM + col] = make_float2(O[nt][2] * inv1, O[nt][3] * inv1);
    }
}

/* ================= launch ================= */
extern "C" void kernel_launch(void* const* d_in, const int* in_sizes, int n_in,
                              void* d_out, int out_size)
{
    const float* x    = (const float*)d_in[0];
    const float* fcos = (const float*)d_in[3];
    const float* fsin = (const float*)d_in[4];
    const float* Wq = (const float*)d_in[5];  const float* bq = (const float*)d_in[6];
    const float* Wk = (const float*)d_in[7];  const float* bk = (const float*)d_in[8];
    const float* Wv = (const float*)d_in[9];  const float* bv = (const float*)d_in[10];
    const float* Wo = (const float*)d_in[11]; const float* bo = (const float*)d_in[12];
    const float* gq = (const float*)d_in[13]; const float* gk = (const float*)d_in[14];
    float* out = (float*)d_out;

    float *dq, *dk, *dv, *dobuf;
    cudaGetSymbolAddress((void**)&dq,    g_q);
    cudaGetSymbolAddress((void**)&dk,    g_k);
    cudaGetSymbolAddress((void**)&dv,    g_v);
    cudaGetSymbolAddress((void**)&dobuf, g_o);

    const dim3 gemm_grid(DIM / BN, (S_TOK + BM - 1) / BM);

    gemm_tf32_kernel<<<gemm_grid, 256>>>(x, Wq, bq, dq, S_TOK, DIM, DIM);
    gemm_tf32_kernel<<<gemm_grid, 256>>>(x, Wk, bk, dk, S_TOK, DIM, DIM);
    gemm_tf32_kernel<<<gemm_grid, 256>>>(x, Wv, bv, dv, S_TOK, DIM, DIM);

    rms_rope_kernel<<<dim3(S_TOK, 2), 256>>>(fcos, fsin, gq, gk);

    const int smem_attn = ATTN_SMEM_FLOATS * sizeof(float);
    cudaFuncSetAttribute(attn_mma_kernel, cudaFuncAttributeMaxDynamicSharedMemorySize, smem_attn);
    attn_mma_kernel<<<dim3((S_TOK + 63) / 64, NH), 128, smem_attn>>>();

    gemm_tf32_kernel<<<gemm_grid, 256>>>(dobuf, Wo, bo, out, S_TOK, DIM, DIM);
}

// round 6
// speedup vs baseline: 3.1023x; 1.8818x over previous
#include <cuda_runtime.h>
#include <cuda_fp16.h>
#include <math.h>
#include <stdint.h>

#define S_TOK 3120
#define DIM   1536
#define NH    12
#define HD    128
#define FRAME 520
#define TK    64
#define GK    1536

/* ---- scratch (static device globals) ---- */
__device__ float  g_q[S_TOK * DIM];
__device__ float  g_k[S_TOK * DIM];
__device__ float  g_v[S_TOK * DIM];
__device__ __half g_oh[S_TOK * DIM];          /* attention output, half      */
__device__ __half g_xh[S_TOK * DIM];          /* x converted to half         */
__device__ __half g_wTh[4][GK * GK];          /* W^T converted to half       */

__device__ __forceinline__ void mma_f16(float* c, const uint32_t* a, uint32_t b0, uint32_t b1) {
    asm volatile(
        "mma.sync.aligned.m16n8k16.row.col.f32.f16.f16.f32 "
        "{%0,%1,%2,%3}, {%4,%5,%6,%7}, {%8,%9}, {%0,%1,%2,%3};"
        : "+f"(c[0]), "+f"(c[1]), "+f"(c[2]), "+f"(c[3])
        : "r"(a[0]), "r"(a[1]), "r"(a[2]), "r"(a[3]), "r"(b0), "r"(b1));
}

__device__ __forceinline__ void cp_async16(void* smem_dst, const void* gsrc, bool valid) {
    uint32_t saddr = (uint32_t)__cvta_generic_to_shared(smem_dst);
    int sz = valid ? 16 : 0;
    asm volatile("cp.async.cg.shared.global [%0], [%1], 16, %2;\n"
                 :: "r"(saddr), "l"(gsrc), "r"(sz));
}
__device__ __forceinline__ void cp_commit() { asm volatile("cp.async.commit_group;\n"); }
template <int N>
__device__ __forceinline__ void cp_wait() { asm volatile("cp.async.wait_group %0;\n" :: "n"(N)); }

/* ============== pre-pass kernels ============== */
__global__ __launch_bounds__(256) void transpose_half_kernel(
    const float* __restrict__ w0, const float* __restrict__ w1,
    const float* __restrict__ w2, const float* __restrict__ w3,
    __half* __restrict__ dstbase)
{
    __shared__ float tile[32][33];
    const float* src = (blockIdx.z == 0) ? w0 : (blockIdx.z == 1) ? w1 : (blockIdx.z == 2) ? w2 : w3;
    __half* dst = dstbase + (size_t)blockIdx.z * GK * GK;
    const int tx = threadIdx.x & 31, ty = threadIdx.x >> 5;
    int x = blockIdx.x * 32 + tx;
    int y = blockIdx.y * 32 + ty;
#pragma unroll
    for (int i = 0; i < 32; i += 8)
        tile[ty + i][tx] = src[(size_t)(y + i) * GK + x];
    __syncthreads();
    x = blockIdx.y * 32 + tx;
    y = blockIdx.x * 32 + ty;
#pragma unroll
    for (int i = 0; i < 32; i += 8)
        dst[(size_t)(y + i) * GK + x] = __float2half_rn(tile[tx][ty + i]);
}

__global__ __launch_bounds__(256) void convert_x_kernel(const float* __restrict__ x)
{
    int i = (blockIdx.x * 256 + threadIdx.x) * 4;
    if (i < S_TOK * DIM) {
        float4 v = *(const float4*)&x[i];
        __half2 h0 = __floats2half2_rn(v.x, v.y);
        __half2 h1 = __floats2half2_rn(v.z, v.w);
        *(__half2*)&g_xh[i]     = h0;
        *(__half2*)&g_xh[i + 2] = h1;
    }
}

/* ============== fp16 tensor-core GEMM: C[M,N] = A @ Bt^T + bias ============== */
/* A: [M][K] half row-major. Bt: [N][K] half row-major (= W^T).                 */
#define BM 128
#define BN 128
#define BKH 32                 /* K-chunk in halves */
#define GST 40                 /* smem row stride in halves (80B): banks 20r+c all distinct */

__global__ __launch_bounds__(128, 2) void gemm_f16_kernel(
    const __half* __restrict__ A, const __half* __restrict__ Bt,
    const float* __restrict__ bias, float* __restrict__ C, int M)
{
    __shared__ __half As[2][BM][GST];
    __shared__ __half Bs[2][BN][GST];

    const int tid  = threadIdx.x;
    const int warp = tid >> 5;
    const int lane = tid & 31;
    const int gr   = lane >> 2;
    const int gc   = lane & 3;

    const int bm = blockIdx.y * BM;
    const int bn = blockIdx.x * BN;
    const int wm = (warp & 1) * 64;
    const int wn = (warp >> 1) * 64;

    float acc[4][8][4];
#pragma unroll
    for (int mi = 0; mi < 4; mi++)
#pragma unroll
        for (int nj = 0; nj < 8; nj++)
#pragma unroll
            for (int e = 0; e < 4; e++) acc[mi][nj][e] = 0.f;

    /* copy slots: 4 chunks of 16B per tile per thread (128 rows x 4 chunks) */
    int crow[4]; int cc16[4];
#pragma unroll
    for (int i = 0; i < 4; i++) {
        const int cid = i * 128 + tid;
        crow[i] = cid >> 2;
        cc16[i] = cid & 3;
    }

    const int NT = GK / BKH;   /* 48 */

    /* prologue: chunk 0 */
#pragma unroll
    for (int i = 0; i < 4; i++) {
        cp_async16(&As[0][crow[i]][cc16[i] * 8], &A[(size_t)(bm + crow[i]) * GK + cc16[i] * 8], (bm + crow[i]) < M);
        cp_async16(&Bs[0][crow[i]][cc16[i] * 8], &Bt[(size_t)(bn + crow[i]) * GK + cc16[i] * 8], true);
    }
    cp_commit();

    for (int t = 0; t < NT; t++) {
        if (t + 1 < NT) {
            const int kt = (t + 1) * BKH;
            const int s1 = (t + 1) & 1;
#pragma unroll
            for (int i = 0; i < 4; i++) {
                cp_async16(&As[s1][crow[i]][cc16[i] * 8], &A[(size_t)(bm + crow[i]) * GK + kt + cc16[i] * 8], (bm + crow[i]) < M);
                cp_async16(&Bs[s1][crow[i]][cc16[i] * 8], &Bt[(size_t)(bn + crow[i]) * GK + kt + cc16[i] * 8], true);
            }
        }
        cp_commit();
        cp_wait<1>();
        __syncthreads();

        const int b = t & 1;
#pragma unroll
        for (int ks = 0; ks < 2; ks++) {
            const int kh = ks * 16 + 2 * gc;
            uint32_t af[4][4];
#pragma unroll
            for (int mi = 0; mi < 4; mi++) {
                const int m0 = wm + mi * 16 + gr;
                af[mi][0] = *(const uint32_t*)&As[b][m0][kh];
                af[mi][1] = *(const uint32_t*)&As[b][m0 + 8][kh];
                af[mi][2] = *(const uint32_t*)&As[b][m0][kh + 8];
                af[mi][3] = *(const uint32_t*)&As[b][m0 + 8][kh + 8];
            }
#pragma unroll
            for (int nj = 0; nj < 8; nj++) {
                const int n0 = wn + nj * 8 + gr;
                uint32_t b0 = *(const uint32_t*)&Bs[b][n0][kh];
                uint32_t b1 = *(const uint32_t*)&Bs[b][n0][kh + 8];
#pragma unroll
                for (int mi = 0; mi < 4; mi++)
                    mma_f16(acc[mi][nj], af[mi], b0, b1);
            }
        }
        __syncthreads();
    }

    /* epilogue: bias + store fp32 */
#pragma unroll
    for (int mi = 0; mi < 4; mi++) {
        const int row0 = bm + wm + mi * 16 + gr;
        const int row1 = row0 + 8;
#pragma unroll
        for (int nj = 0; nj < 8; nj++) {
            const int col = bn + wn + nj * 8 + 2 * gc;
            const float b0 = bias[col];
            const float b1 = bias[col + 1];
            if (row0 < M)
                *(float2*)&C[(size_t)row0 * GK + col] = make_float2(acc[mi][nj][0] + b0, acc[mi][nj][1] + b1);
            if (row1 < M)
                *(float2*)&C[(size_t)row1 * GK + col] = make_float2(acc[mi][nj][2] + b0, acc[mi][nj][3] + b1);
        }
    }
}

/* ============ fused RMSNorm + 3-axis RoPE, in place ============ */
__global__ __launch_bounds__(256) void rms_rope_kernel(
    const float* __restrict__ fcos, const float* __restrict__ fsin,
    const float* __restrict__ gq, const float* __restrict__ gk)
{
    const int row   = blockIdx.x;
    const int which = blockIdx.y;
    float* buf      = which ? g_k : g_q;
    const float* g  = which ? gk : gq;
    const int tid   = threadIdx.x;

    const float* p = buf + (size_t)row * DIM;
    float ss = 0.f;
    for (int i = tid; i < DIM; i += 256) { float v = p[i]; ss += v * v; }

    __shared__ float red[256];
    red[tid] = ss;
    __syncthreads();
    for (int s = 128; s > 0; s >>= 1) {
        if (tid < s) red[tid] += red[tid + s];
        __syncthreads();
    }
    const float inv = rsqrtf(red[0] * (1.0f / DIM) + 1e-6f);

    const int f  = row / FRAME;
    const int hh = (row / 26) % 20;
    const int ww = row % 26;

    for (int pi = tid; pi < NH * 64; pi += 256) {
        const int head = pi >> 6;
        const int c    = pi & 63;
        const int pr   = (c < 22) ? f : ((c < 43) ? hh : ww);
        const float cs = fcos[pr * 64 + c];
        const float sn = fsin[pr * 64 + c];
        const size_t base = (size_t)row * DIM + head * HD + 2 * c;
        const float xr = buf[base]     * inv * g[head * HD + 2 * c];
        const float xi = buf[base + 1] * inv * g[head * HD + 2 * c + 1];
        buf[base]     = xr * cs - xi * sn;
        buf[base + 1] = xr * sn + xi * cs;
    }
}

/* ========== fp16 tensor-core flash attention (compensated QK) ========== */
/* smem strides (halves): QS=136 (272B -> banks 4r+c), VS=72 (144B -> 4r+c), PS=72 */
#define QS 136
#define VS 72
#define PS 72
#define OFF_QH 0
#define OFF_QL (64 * QS)
#define OFF_KH (2 * 64 * QS)
#define OFF_KL (3 * 64 * QS)
#define OFF_VT (4 * 64 * QS)
#define OFF_PS (4 * 64 * QS + 128 * VS)
#define ATTN_SMEM_BYTES ((4 * 64 * QS + 128 * VS + 64 * PS) * 2)

__global__ __launch_bounds__(128) void attn_f16_kernel()
{
    extern __shared__ __half sh[];
    __half* Qh = sh + OFF_QH;
    __half* Ql = sh + OFF_QL;
    __half* Kh = sh + OFF_KH;
    __half* Kl = sh + OFF_KL;
    __half* Vt = sh + OFF_VT;
    __half* Ps = sh + OFF_PS;

    const int tid  = threadIdx.x;
    const int warp = tid >> 5;
    const int lane = tid & 31;
    const int gr   = lane >> 2;
    const int gc   = lane & 3;
    const int qs   = blockIdx.x * 64;
    const int h    = blockIdx.y;

    /* load Q tile: hi/lo fp16 split */
    {
        const int r  = tid >> 1;
        const int c0 = (tid & 1) * 64;
        const bool valid = (qs + r) < S_TOK;
        const float* src = &g_q[(size_t)(qs + r) * DIM + h * HD + c0];
#pragma unroll
        for (int i = 0; i < 16; i++) {
            float4 x = valid ? *(const float4*)(src + i * 4) : make_float4(0.f, 0.f, 0.f, 0.f);
            __half hx = __float2half_rn(x.x), hy = __float2half_rn(x.y);
            __half hz = __float2half_rn(x.z), hw = __float2half_rn(x.w);
            *(__half2*)&Qh[r * QS + c0 + i * 4]     = __halves2half2(hx, hy);
            *(__half2*)&Qh[r * QS + c0 + i * 4 + 2] = __halves2half2(hz, hw);
            *(__half2*)&Ql[r * QS + c0 + i * 4] =
                __floats2half2_rn(x.x - __half2float(hx), x.y - __half2float(hy));
            *(__half2*)&Ql[r * QS + c0 + i * 4 + 2] =
                __floats2half2_rn(x.z - __half2float(hz), x.w - __half2float(hw));
        }
    }

    const int row_l0 = warp * 16 + gr;
    const int row_l1 = row_l0 + 8;
    const int fi0 = (qs + row_l0) / FRAME;
    const int fi1 = (qs + row_l1) / FRAME;

    float m0 = -1e30f, m1 = -1e30f, l0 = 0.f, l1 = 0.f;
    float O[16][4];
#pragma unroll
    for (int nt = 0; nt < 16; nt++)
#pragma unroll
        for (int e = 0; e < 4; e++) O[nt][e] = 0.f;

    const int fi_min = qs / FRAME;
    const int fi_max = min(qs + 63, S_TOK - 1) / FRAME;
    int lo = fi_min - 3; if (lo < 0) lo = 0;
    lo *= FRAME;
    int hi = (fi_max + 1) * FRAME; if (hi > S_TOK) hi = S_TOK;
    int starts[2], ends[2], nr;
    if (lo <= FRAME) { nr = 1; starts[0] = 0; ends[0] = hi; }
    else { nr = 2; starts[0] = 0; ends[0] = FRAME; starts[1] = (lo / TK) * TK; ends[1] = hi; }

    const float scale = 0.08838834764831845f;

    for (int rr = 0; rr < nr; rr++)
    for (int ks0 = starts[rr]; ks0 < ends[rr]; ks0 += TK) {
        __syncthreads();

        /* K tile: hi/lo split */
        {
            const int r  = tid >> 1;
            const int c0 = (tid & 1) * 64;
            const bool valid = (ks0 + r) < S_TOK;
            const float* src = &g_k[(size_t)(ks0 + r) * DIM + h * HD + c0];
#pragma unroll
            for (int i = 0; i < 16; i++) {
                float4 x = valid ? *(const float4*)(src + i * 4) : make_float4(0.f, 0.f, 0.f, 0.f);
                __half hx = __float2half_rn(x.x), hy = __float2half_rn(x.y);
                __half hz = __float2half_rn(x.z), hw = __float2half_rn(x.w);
                *(__half2*)&Kh[r * QS + c0 + i * 4]     = __halves2half2(hx, hy);
                *(__half2*)&Kh[r * QS + c0 + i * 4 + 2] = __halves2half2(hz, hw);
                *(__half2*)&Kl[r * QS + c0 + i * 4] =
                    __floats2half2_rn(x.x - __half2float(hx), x.y - __half2float(hy));
                *(__half2*)&Kl[r * QS + c0 + i * 4 + 2] =
                    __floats2half2_rn(x.z - __half2float(hz), x.w - __half2float(hw));
            }
        }
        /* V tile, transposed: Vt[d][key] */
        {
#pragma unroll 4
            for (int rr2 = 0; rr2 < 16; rr2++) {
                const int r = warp * 16 + rr2;
                const bool valid = (ks0 + r) < S_TOK;
                const float* src = &g_v[(size_t)(ks0 + r) * DIM + h * HD];
#pragma unroll
                for (int d0 = 0; d0 < 128; d0 += 32) {
                    float x = valid ? src[d0 + lane] : 0.f;
                    Vt[(d0 + lane) * VS + r] = __float2half_rn(x);
                }
            }
        }
        __syncthreads();

        /* ---- QK^T (3-term compensated fp16) ---- */
        float Sa[8][4];
#pragma unroll
        for (int nj = 0; nj < 8; nj++)
#pragma unroll
            for (int e = 0; e < 4; e++) Sa[nj][e] = 0.f;

#pragma unroll
        for (int ks = 0; ks < 8; ks++) {
            const int kh = ks * 16 + 2 * gc;
            uint32_t ah[4], al[4];
            ah[0] = *(const uint32_t*)&Qh[row_l0 * QS + kh];
            ah[1] = *(const uint32_t*)&Qh[row_l1 * QS + kh];
            ah[2] = *(const uint32_t*)&Qh[row_l0 * QS + kh + 8];
            ah[3] = *(const uint32_t*)&Qh[row_l1 * QS + kh + 8];
            al[0] = *(const uint32_t*)&Ql[row_l0 * QS + kh];
            al[1] = *(const uint32_t*)&Ql[row_l1 * QS + kh];
            al[2] = *(const uint32_t*)&Ql[row_l0 * QS + kh + 8];
            al[3] = *(const uint32_t*)&Ql[row_l1 * QS + kh + 8];
#pragma unroll
            for (int nj = 0; nj < 8; nj++) {
                const int n = nj * 8 + gr;
                uint32_t bh0 = *(const uint32_t*)&Kh[n * QS + kh];
                uint32_t bh1 = *(const uint32_t*)&Kh[n * QS + kh + 8];
                uint32_t bl0 = *(const uint32_t*)&Kl[n * QS + kh];
                uint32_t bl1 = *(const uint32_t*)&Kl[n * QS + kh + 8];
                mma_f16(Sa[nj], ah, bh0, bh1);
                mma_f16(Sa[nj], al, bh0, bh1);
                mma_f16(Sa[nj], ah, bl0, bl1);
            }
        }

        /* ---- scale + frame mask ---- */
        float mloc0 = -1e30f, mloc1 = -1e30f;
#pragma unroll
        for (int nj = 0; nj < 8; nj++) {
            const int cg = ks0 + nj * 8 + 2 * gc;
            const int fj = cg / FRAME;
            const bool kv = (cg < S_TOK);
            const bool ok0 = kv && (fj <= fi0) && (((fi0 - fj) < 4) || (fj == 0));
            const bool ok1 = kv && (fj <= fi1) && (((fi1 - fj) < 4) || (fj == 0));
            Sa[nj][0] = ok0 ? Sa[nj][0] * scale : -1e30f;
            Sa[nj][1] = ok0 ? Sa[nj][1] * scale : -1e30f;
            Sa[nj][2] = ok1 ? Sa[nj][2] * scale : -1e30f;
            Sa[nj][3] = ok1 ? Sa[nj][3] * scale : -1e30f;
            mloc0 = fmaxf(mloc0, fmaxf(Sa[nj][0], Sa[nj][1]));
            mloc1 = fmaxf(mloc1, fmaxf(Sa[nj][2], Sa[nj][3]));
        }
        mloc0 = fmaxf(mloc0, __shfl_xor_sync(0xffffffffu, mloc0, 1));
        mloc0 = fmaxf(mloc0, __shfl_xor_sync(0xffffffffu, mloc0, 2));
        mloc1 = fmaxf(mloc1, __shfl_xor_sync(0xffffffffu, mloc1, 1));
        mloc1 = fmaxf(mloc1, __shfl_xor_sync(0xffffffffu, mloc1, 2));

        const float mn0 = fmaxf(m0, mloc0);
        const float mn1 = fmaxf(m1, mloc1);
        const float a0 = __expf(m0 - mn0);
        const float a1 = __expf(m1 - mn1);
        m0 = mn0; m1 = mn1;

        float ls0 = 0.f, ls1 = 0.f;
#pragma unroll
        for (int nj = 0; nj < 8; nj++) {
            const int cc = nj * 8 + 2 * gc;
            float p00 = __expf(Sa[nj][0] - mn0);
            float p01 = __expf(Sa[nj][1] - mn0);
            float p10 = __expf(Sa[nj][2] - mn1);
            float p11 = __expf(Sa[nj][3] - mn1);
            ls0 += p00 + p01;
            ls1 += p10 + p11;
            *(__half2*)&Ps[row_l0 * PS + cc] = __floats2half2_rn(p00, p01);
            *(__half2*)&Ps[row_l1 * PS + cc] = __floats2half2_rn(p10, p11);
        }
        ls0 += __shfl_xor_sync(0xffffffffu, ls0, 1);
        ls0 += __shfl_xor_sync(0xffffffffu, ls0, 2);
        ls1 += __shfl_xor_sync(0xffffffffu, ls1, 1);
        ls1 += __shfl_xor_sync(0xffffffffu, ls1, 2);
        l0 = l0 * a0 + ls0;
        l1 = l1 * a1 + ls1;

#pragma unroll
        for (int nt = 0; nt < 16; nt++) {
            O[nt][0] *= a0; O[nt][1] *= a0;
            O[nt][2] *= a1; O[nt][3] *= a1;
        }
        __syncwarp();

        /* ---- P @ V ---- */
#pragma unroll
        for (int ks = 0; ks < 4; ks++) {
            const int kh = ks * 16 + 2 * gc;
            uint32_t pa[4];
            pa[0] = *(const uint32_t*)&Ps[row_l0 * PS + kh];
            pa[1] = *(const uint32_t*)&Ps[row_l1 * PS + kh];
            pa[2] = *(const uint32_t*)&Ps[row_l0 * PS + kh + 8];
            pa[3] = *(const uint32_t*)&Ps[row_l1 * PS + kh + 8];
#pragma unroll
            for (int nt = 0; nt < 16; nt++) {
                const int d = nt * 8 + gr;
                uint32_t b0 = *(const uint32_t*)&Vt[d * VS + kh];
                uint32_t b1 = *(const uint32_t*)&Vt[d * VS + kh + 8];
                mma_f16(O[nt], pa, b0, b1);
            }
        }
    }

    /* normalize + store as half (feeds output GEMM) */
    const float inv0 = 1.f / l0;
    const float inv1 = 1.f / l1;
    const int rg0 = qs + row_l0;
    const int rg1 = qs + row_l1;
#pragma unroll
    for (int nt = 0; nt < 16; nt++) {
        const int col = h * HD + nt * 8 + 2 * gc;
        if (rg0 < S_TOK)
            *(__half2*)&g_oh[(size_t)rg0 * DIM + col] = __floats2half2_rn(O[nt][0] * inv0, O[nt][1] * inv0);
        if (rg1 < S_TOK)
            *(__half2*)&g_oh[(size_t)rg1 * DIM + col] = __floats2half2_rn(O[nt][2] * inv1, O[nt][3] * inv1);
    }
}

/* ================= launch ================= */
extern "C" void kernel_launch(void* const* d_in, const int* in_sizes, int n_in,
                              void* d_out, int out_size)
{
    const float* x    = (const float*)d_in[0];
    const float* fcos = (const float*)d_in[3];
    const float* fsin = (const float*)d_in[4];
    const float* Wq = (const float*)d_in[5];  const float* bq = (const float*)d_in[6];
    const float* Wk = (const float*)d_in[7];  const float* bk = (const float*)d_in[8];
    const float* Wv = (const float*)d_in[9];  const float* bv = (const float*)d_in[10];
    const float* Wo = (const float*)d_in[11]; const float* bo = (const float*)d_in[12];
    const float* gq = (const float*)d_in[13]; const float* gk = (const float*)d_in[14];
    float* out = (float*)d_out;

    float *dq, *dk, *dv;
    __half *doh, *dxh, *dwTh;
    cudaGetSymbolAddress((void**)&dq,   g_q);
    cudaGetSymbolAddress((void**)&dk,   g_k);
    cudaGetSymbolAddress((void**)&dv,   g_v);
    cudaGetSymbolAddress((void**)&doh,  g_oh);
    cudaGetSymbolAddress((void**)&dxh,  g_xh);
    cudaGetSymbolAddress((void**)&dwTh, g_wTh);

    /* pre-pass: W transposes (-> half) + x conversion */
    transpose_half_kernel<<<dim3(48, 48, 4), 256>>>(Wq, Wk, Wv, Wo, dwTh);
    convert_x_kernel<<<(S_TOK * DIM / 4 + 255) / 256, 256>>>(x);

    const dim3 gemm_grid(GK / BN, (S_TOK + BM - 1) / BM);   /* (12, 25) */

    gemm_f16_kernel<<<gemm_grid, 128>>>(dxh, dwTh + 0 * (size_t)GK * GK, bq, dq, S_TOK);
    gemm_f16_kernel<<<gemm_grid, 128>>>(dxh, dwTh + 1 * (size_t)GK * GK, bk, dk, S_TOK);
    gemm_f16_kernel<<<gemm_grid, 128>>>(dxh, dwTh + 2 * (size_t)GK * GK, bv, dv, S_TOK);

    rms_rope_kernel<<<dim3(S_TOK, 2), 256>>>(fcos, fsin, gq, gk);

    cudaFuncSetAttribute(attn_f16_kernel, cudaFuncAttributeMaxDynamicSharedMemorySize, ATTN_SMEM_BYTES);
    attn_f16_kernel<<<dim3((S_TOK + 63) / 64, NH), 128, ATTN_SMEM_BYTES>>>();

    gemm_f16_kernel<<<gemm_grid, 128>>>(doh, dwTh + 3 * (size_t)GK * GK, bo, out, S_TOK);
}

// round 7
// speedup vs baseline: 4.6175x; 1.4884x over previous
#include <cuda_runtime.h>
#include <cuda_fp16.h>
#include <math.h>
#include <stdint.h>

#define S_TOK 3120
#define DIM   1536
#define NH    12
#define HD    128
#define FRAME 520
#define TK    64
#define GK    1536
#define VT_PAD 3136   /* 49*64, token padding for transposed V */

/* ---- scratch (static device globals) ---- */
__device__ float  g_q[S_TOK * DIM];
__device__ float  g_k[S_TOK * DIM];
__device__ float  g_v[S_TOK * DIM];
__device__ __half g_oh[S_TOK * DIM];          /* attention output, half    */
__device__ __half g_xh[S_TOK * DIM];          /* x converted to half       */
__device__ __half g_wTh[4][GK * GK];          /* W^T converted to half     */
__device__ __half g_qhh[S_TOK * DIM];         /* rope(q) hi                */
__device__ __half g_qll[S_TOK * DIM];         /* rope(q) lo                */
__device__ __half g_khh[S_TOK * DIM];         /* rope(k) hi                */
__device__ __half g_kll[S_TOK * DIM];         /* rope(k) lo                */
__device__ __half g_vt[NH * HD * VT_PAD];     /* V transposed [h][d][tok]  */

__device__ __forceinline__ void mma_f16(float* c, const uint32_t* a, uint32_t b0, uint32_t b1) {
    asm volatile(
        "mma.sync.aligned.m16n8k16.row.col.f32.f16.f16.f32 "
        "{%0,%1,%2,%3}, {%4,%5,%6,%7}, {%8,%9}, {%0,%1,%2,%3};"
        : "+f"(c[0]), "+f"(c[1]), "+f"(c[2]), "+f"(c[3])
        : "r"(a[0]), "r"(a[1]), "r"(a[2]), "r"(a[3]), "r"(b0), "r"(b1));
}

__device__ __forceinline__ void cp_async16(void* smem_dst, const void* gsrc, bool valid) {
    uint32_t saddr = (uint32_t)__cvta_generic_to_shared(smem_dst);
    int sz = valid ? 16 : 0;
    asm volatile("cp.async.cg.shared.global [%0], [%1], 16, %2;\n"
                 :: "r"(saddr), "l"(gsrc), "r"(sz));
}
__device__ __forceinline__ void cp_commit() { asm volatile("cp.async.commit_group;\n"); }
template <int N>
__device__ __forceinline__ void cp_wait() { asm volatile("cp.async.wait_group %0;\n" :: "n"(N)); }

/* ============== pre-pass kernels ============== */
__global__ __launch_bounds__(256) void transpose_half_kernel(
    const float* __restrict__ w0, const float* __restrict__ w1,
    const float* __restrict__ w2, const float* __restrict__ w3,
    __half* __restrict__ dstbase)
{
    __shared__ float tile[32][33];
    const float* src = (blockIdx.z == 0) ? w0 : (blockIdx.z == 1) ? w1 : (blockIdx.z == 2) ? w2 : w3;
    __half* dst = dstbase + (size_t)blockIdx.z * GK * GK;
    const int tx = threadIdx.x & 31, ty = threadIdx.x >> 5;
    int x = blockIdx.x * 32 + tx;
    int y = blockIdx.y * 32 + ty;
#pragma unroll
    for (int i = 0; i < 32; i += 8)
        tile[ty + i][tx] = src[(size_t)(y + i) * GK + x];
    __syncthreads();
    x = blockIdx.y * 32 + tx;
    y = blockIdx.x * 32 + ty;
#pragma unroll
    for (int i = 0; i < 32; i += 8)
        dst[(size_t)(y + i) * GK + x] = __float2half_rn(tile[tx][ty + i]);
}

__global__ __launch_bounds__(256) void convert_x_kernel(const float* __restrict__ x)
{
    int i = (blockIdx.x * 256 + threadIdx.x) * 4;
    if (i < S_TOK * DIM) {
        float4 v = *(const float4*)&x[i];
        *(__half2*)&g_xh[i]     = __floats2half2_rn(v.x, v.y);
        *(__half2*)&g_xh[i + 2] = __floats2half2_rn(v.z, v.w);
    }
}

/* V fp32 [token][DIM] -> half [dim][token] (dim includes head), zero-padded tokens */
__global__ __launch_bounds__(256) void v_trans_kernel()
{
    __shared__ float tile[32][33];
    const int tx = threadIdx.x & 31, ty = threadIdx.x >> 5;
    const int t0 = blockIdx.x * 32;       /* token base */
    const int d0 = blockIdx.y * 32;       /* global dim base */
#pragma unroll
    for (int i = 0; i < 32; i += 8) {
        const int tok = t0 + ty + i;
        tile[ty + i][tx] = (tok < S_TOK) ? g_v[(size_t)tok * DIM + d0 + tx] : 0.f;
    }
    __syncthreads();
#pragma unroll
    for (int i = 0; i < 32; i += 8) {
        const int d = d0 + ty + i;
        g_vt[(size_t)d * VT_PAD + t0 + tx] = __float2half_rn(tile[tx][ty + i]);
    }
}

/* ============== fp16 tensor-core GEMM (unchanged from R6) ============== */
#define BM 128
#define BN 128
#define BKH 32
#define GST 40

__global__ __launch_bounds__(128, 2) void gemm_f16_kernel(
    const __half* __restrict__ A, const __half* __restrict__ Bt,
    const float* __restrict__ bias, float* __restrict__ C, int M)
{
    __shared__ __half As[2][BM][GST];
    __shared__ __half Bs[2][BN][GST];

    const int tid  = threadIdx.x;
    const int warp = tid >> 5;
    const int lane = tid & 31;
    const int gr   = lane >> 2;
    const int gc   = lane & 3;

    const int bm = blockIdx.y * BM;
    const int bn = blockIdx.x * BN;
    const int wm = (warp & 1) * 64;
    const int wn = (warp >> 1) * 64;

    float acc[4][8][4];
#pragma unroll
    for (int mi = 0; mi < 4; mi++)
#pragma unroll
        for (int nj = 0; nj < 8; nj++)
#pragma unroll
            for (int e = 0; e < 4; e++) acc[mi][nj][e] = 0.f;

    int crow[4]; int cc16[4];
#pragma unroll
    for (int i = 0; i < 4; i++) {
        const int cid = i * 128 + tid;
        crow[i] = cid >> 2;
        cc16[i] = cid & 3;
    }

    const int NT = GK / BKH;

#pragma unroll
    for (int i = 0; i < 4; i++) {
        cp_async16(&As[0][crow[i]][cc16[i] * 8], &A[(size_t)(bm + crow[i]) * GK + cc16[i] * 8], (bm + crow[i]) < M);
        cp_async16(&Bs[0][crow[i]][cc16[i] * 8], &Bt[(size_t)(bn + crow[i]) * GK + cc16[i] * 8], true);
    }
    cp_commit();

    for (int t = 0; t < NT; t++) {
        if (t + 1 < NT) {
            const int kt = (t + 1) * BKH;
            const int s1 = (t + 1) & 1;
#pragma unroll
            for (int i = 0; i < 4; i++) {
                cp_async16(&As[s1][crow[i]][cc16[i] * 8], &A[(size_t)(bm + crow[i]) * GK + kt + cc16[i] * 8], (bm + crow[i]) < M);
                cp_async16(&Bs[s1][crow[i]][cc16[i] * 8], &Bt[(size_t)(bn + crow[i]) * GK + kt + cc16[i] * 8], true);
            }
        }
        cp_commit();
        cp_wait<1>();
        __syncthreads();

        const int b = t & 1;
#pragma unroll
        for (int ks = 0; ks < 2; ks++) {
            const int kh = ks * 16 + 2 * gc;
            uint32_t af[4][4];
#pragma unroll
            for (int mi = 0; mi < 4; mi++) {
                const int m0 = wm + mi * 16 + gr;
                af[mi][0] = *(const uint32_t*)&As[b][m0][kh];
                af[mi][1] = *(const uint32_t*)&As[b][m0 + 8][kh];
                af[mi][2] = *(const uint32_t*)&As[b][m0][kh + 8];
                af[mi][3] = *(const uint32_t*)&As[b][m0 + 8][kh + 8];
            }
#pragma unroll
            for (int nj = 0; nj < 8; nj++) {
                const int n0 = wn + nj * 8 + gr;
                uint32_t b0 = *(const uint32_t*)&Bs[b][n0][kh];
                uint32_t b1 = *(const uint32_t*)&Bs[b][n0][kh + 8];
#pragma unroll
                for (int mi = 0; mi < 4; mi++)
                    mma_f16(acc[mi][nj], af[mi], b0, b1);
            }
        }
        __syncthreads();
    }

#pragma unroll
    for (int mi = 0; mi < 4; mi++) {
        const int row0 = bm + wm + mi * 16 + gr;
        const int row1 = row0 + 8;
#pragma unroll
        for (int nj = 0; nj < 8; nj++) {
            const int col = bn + wn + nj * 8 + 2 * gc;
            const float b0 = bias[col];
            const float b1 = bias[col + 1];
            if (row0 < M)
                *(float2*)&C[(size_t)row0 * GK + col] = make_float2(acc[mi][nj][0] + b0, acc[mi][nj][1] + b1);
            if (row1 < M)
                *(float2*)&C[(size_t)row1 * GK + col] = make_float2(acc[mi][nj][2] + b0, acc[mi][nj][3] + b1);
        }
    }
}

/* ============ fused RMSNorm + RoPE -> half hi/lo global arrays ============ */
__global__ __launch_bounds__(256) void rms_rope_kernel(
    const float* __restrict__ fcos, const float* __restrict__ fsin,
    const float* __restrict__ gq, const float* __restrict__ gk)
{
    const int row   = blockIdx.x;
    const int which = blockIdx.y;
    const float* buf = which ? g_k : g_q;
    __half* dh       = which ? g_khh : g_qhh;
    __half* dl       = which ? g_kll : g_qll;
    const float* g   = which ? gk : gq;
    const int tid    = threadIdx.x;

    const float* p = buf + (size_t)row * DIM;
    float ss = 0.f;
    for (int i = tid; i < DIM; i += 256) { float v = p[i]; ss += v * v; }

    __shared__ float red[256];
    red[tid] = ss;
    __syncthreads();
    for (int s = 128; s > 0; s >>= 1) {
        if (tid < s) red[tid] += red[tid + s];
        __syncthreads();
    }
    const float inv = rsqrtf(red[0] * (1.0f / DIM) + 1e-6f);

    const int f  = row / FRAME;
    const int hh = (row / 26) % 20;
    const int ww = row % 26;

    for (int pi = tid; pi < NH * 64; pi += 256) {
        const int head = pi >> 6;
        const int c    = pi & 63;
        const int pr   = (c < 22) ? f : ((c < 43) ? hh : ww);
        const float cs = fcos[pr * 64 + c];
        const float sn = fsin[pr * 64 + c];
        const size_t base = (size_t)row * DIM + head * HD + 2 * c;
        const float xr = buf[base]     * inv * g[head * HD + 2 * c];
        const float xi = buf[base + 1] * inv * g[head * HD + 2 * c + 1];
        const float r0 = xr * cs - xi * sn;
        const float r1 = xr * sn + xi * cs;
        const __half h0 = __float2half_rn(r0);
        const __half h1 = __float2half_rn(r1);
        *(__half2*)&dh[base] = __halves2half2(h0, h1);
        *(__half2*)&dl[base] = __floats2half2_rn(r0 - __half2float(h0), r1 - __half2float(h1));
    }
}

/* ========== fp16 flash attention: 128q x 64k, double-buffered cp.async ========== */
#define TQ2 128
#define QS 136
#define VS 72
#define PS 72
#define O_QH 0
#define O_QL (TQ2 * QS)               /* 17408 */
#define O_K  (2 * TQ2 * QS)           /* 34816 */
#define K_STG (2 * 64 * QS)           /* 17408 per stage (hi+lo) */
#define O_V  (O_K + 2 * K_STG)        /* 69632 */
#define V_STG (HD * VS)               /* 9216 */
#define O_P  (O_V + 2 * V_STG)        /* 88064 */
#define ATTN_HALVES (O_P + TQ2 * PS)  /* 97280 */
#define ATTN_SMEM_BYTES (ATTN_HALVES * 2)

__global__ __launch_bounds__(256) void attn_f16_kernel()
{
    extern __shared__ __half sh[];
    const int tid  = threadIdx.x;
    const int warp = tid >> 5;
    const int lane = tid & 31;
    const int gr   = lane >> 2;
    const int gc   = lane & 3;
    const int qs   = blockIdx.x * TQ2;
    const int h    = blockIdx.y;

    /* Q tiles (hi/lo) via cp.async: 128 rows x 16 chunks each */
#pragma unroll
    for (int i = 0; i < 8; i++) {
        const int id = i * 256 + tid;
        const int r = id >> 4, ch = id & 15;
        const bool v = (qs + r) < S_TOK;
        const size_t gsrc = (size_t)(qs + r) * DIM + h * HD + ch * 8;
        cp_async16(sh + O_QH + r * QS + ch * 8, &g_qhh[gsrc], v);
        cp_async16(sh + O_QL + r * QS + ch * 8, &g_qll[gsrc], v);
    }

    /* tile list */
    const int fi_min = qs / FRAME;
    const int fi_max = min(qs + TQ2 - 1, S_TOK - 1) / FRAME;
    int lo = fi_min - 3; if (lo < 0) lo = 0;
    lo *= FRAME;
    int hi = (fi_max + 1) * FRAME; if (hi > S_TOK) hi = S_TOK;
    int tiles[52]; int ntile = 0;
    if (lo <= FRAME) {
        for (int ks = 0; ks < hi; ks += TK) tiles[ntile++] = ks;
    } else {
        for (int ks = 0; ks < FRAME; ks += TK) tiles[ntile++] = ks;
        for (int ks = (lo / TK) * TK; ks < hi; ks += TK) tiles[ntile++] = ks;
    }

    auto load_kv = [&](int ks, int s) {
        __half* Khp = sh + O_K + s * K_STG;
        __half* Klp = Khp + 64 * QS;
        __half* Vp  = sh + O_V + s * V_STG;
#pragma unroll
        for (int i = 0; i < 4; i++) {
            const int id = i * 256 + tid;
            const int r = id >> 4, ch = id & 15;
            const bool v = (ks + r) < S_TOK;
            const size_t gsrc = (size_t)(ks + r) * DIM + h * HD + ch * 8;
            cp_async16(Khp + r * QS + ch * 8, &g_khh[gsrc], v);
            cp_async16(Klp + r * QS + ch * 8, &g_kll[gsrc], v);
        }
#pragma unroll
        for (int i = 0; i < 4; i++) {
            const int id = i * 256 + tid;
            const int d = id >> 3, ch = id & 7;
            cp_async16(Vp + d * VS + ch * 8, &g_vt[(size_t)(h * HD + d) * VT_PAD + ks + ch * 8], true);
        }
    };

    load_kv(tiles[0], 0);
    cp_commit();

    const int row_l0 = warp * 16 + gr;       /* 0..127 */
    const int row_l1 = row_l0 + 8;
    const int fi0 = (qs + row_l0) / FRAME;
    const int fi1 = (qs + row_l1) / FRAME;

    float m0 = -1e30f, m1 = -1e30f, l0 = 0.f, l1 = 0.f;
    float O[16][4];
#pragma unroll
    for (int nt = 0; nt < 16; nt++)
#pragma unroll
        for (int e = 0; e < 4; e++) O[nt][e] = 0.f;

    const float scale = 0.08838834764831845f;
    const __half* Qh = sh + O_QH;
    const __half* Ql = sh + O_QL;
    __half* Ps = sh + O_P;

    for (int it = 0; it < ntile; it++) {
        const int s = it & 1;
        if (it + 1 < ntile) load_kv(tiles[it + 1], s ^ 1);
        cp_commit();
        cp_wait<1>();
        __syncthreads();

        const int ks0 = tiles[it];
        const __half* Kh = sh + O_K + s * K_STG;
        const __half* Kl = Kh + 64 * QS;
        const __half* Vt = sh + O_V + s * V_STG;

        /* ---- QK^T (3-term compensated fp16) ---- */
        float Sa[8][4];
#pragma unroll
        for (int nj = 0; nj < 8; nj++)
#pragma unroll
            for (int e = 0; e < 4; e++) Sa[nj][e] = 0.f;

#pragma unroll
        for (int ks = 0; ks < 8; ks++) {
            const int kh = ks * 16 + 2 * gc;
            uint32_t ah[4], al[4];
            ah[0] = *(const uint32_t*)&Qh[row_l0 * QS + kh];
            ah[1] = *(const uint32_t*)&Qh[row_l1 * QS + kh];
            ah[2] = *(const uint32_t*)&Qh[row_l0 * QS + kh + 8];
            ah[3] = *(const uint32_t*)&Qh[row_l1 * QS + kh + 8];
            al[0] = *(const uint32_t*)&Ql[row_l0 * QS + kh];
            al[1] = *(const uint32_t*)&Ql[row_l1 * QS + kh];
            al[2] = *(const uint32_t*)&Ql[row_l0 * QS + kh + 8];
            al[3] = *(const uint32_t*)&Ql[row_l1 * QS + kh + 8];
#pragma unroll
            for (int nj = 0; nj < 8; nj++) {
                const int n = nj * 8 + gr;
                uint32_t bh0 = *(const uint32_t*)&Kh[n * QS + kh];
                uint32_t bh1 = *(const uint32_t*)&Kh[n * QS + kh + 8];
                uint32_t bl0 = *(const uint32_t*)&Kl[n * QS + kh];
                uint32_t bl1 = *(const uint32_t*)&Kl[n * QS + kh + 8];
                mma_f16(Sa[nj], ah, bh0, bh1);
                mma_f16(Sa[nj], al, bh0, bh1);
                mma_f16(Sa[nj], ah, bl0, bl1);
            }
        }

        /* ---- scale + frame mask ---- */
        float mloc0 = -1e30f, mloc1 = -1e30f;
#pragma unroll
        for (int nj = 0; nj < 8; nj++) {
            const int cg = ks0 + nj * 8 + 2 * gc;
            const int fj = cg / FRAME;
            const bool kv = (cg < S_TOK);
            const bool ok0 = kv && (fj <= fi0) && (((fi0 - fj) < 4) || (fj == 0));
            const bool ok1 = kv && (fj <= fi1) && (((fi1 - fj) < 4) || (fj == 0));
            Sa[nj][0] = ok0 ? Sa[nj][0] * scale : -1e30f;
            Sa[nj][1] = ok0 ? Sa[nj][1] * scale : -1e30f;
            Sa[nj][2] = ok1 ? Sa[nj][2] * scale : -1e30f;
            Sa[nj][3] = ok1 ? Sa[nj][3] * scale : -1e30f;
            mloc0 = fmaxf(mloc0, fmaxf(Sa[nj][0], Sa[nj][1]));
            mloc1 = fmaxf(mloc1, fmaxf(Sa[nj][2], Sa[nj][3]));
        }
        mloc0 = fmaxf(mloc0, __shfl_xor_sync(0xffffffffu, mloc0, 1));
        mloc0 = fmaxf(mloc0, __shfl_xor_sync(0xffffffffu, mloc0, 2));
        mloc1 = fmaxf(mloc1, __shfl_xor_sync(0xffffffffu, mloc1, 1));
        mloc1 = fmaxf(mloc1, __shfl_xor_sync(0xffffffffu, mloc1, 2));

        const float mn0 = fmaxf(m0, mloc0);
        const float mn1 = fmaxf(m1, mloc1);
        const float a0 = __expf(m0 - mn0);
        const float a1 = __expf(m1 - mn1);
        m0 = mn0; m1 = mn1;

        float ls0 = 0.f, ls1 = 0.f;
#pragma unroll
        for (int nj = 0; nj < 8; nj++) {
            const int cc = nj * 8 + 2 * gc;
            float p00 = __expf(Sa[nj][0] - mn0);
            float p01 = __expf(Sa[nj][1] - mn0);
            float p10 = __expf(Sa[nj][2] - mn1);
            float p11 = __expf(Sa[nj][3] - mn1);
            ls0 += p00 + p01;
            ls1 += p10 + p11;
            *(__half2*)&Ps[row_l0 * PS + cc] = __floats2half2_rn(p00, p01);
            *(__half2*)&Ps[row_l1 * PS + cc] = __floats2half2_rn(p10, p11);
        }
        ls0 += __shfl_xor_sync(0xffffffffu, ls0, 1);
        ls0 += __shfl_xor_sync(0xffffffffu, ls0, 2);
        ls1 += __shfl_xor_sync(0xffffffffu, ls1, 1);
        ls1 += __shfl_xor_sync(0xffffffffu, ls1, 2);
        l0 = l0 * a0 + ls0;
        l1 = l1 * a1 + ls1;

#pragma unroll
        for (int nt = 0; nt < 16; nt++) {
            O[nt][0] *= a0; O[nt][1] *= a0;
            O[nt][2] *= a1; O[nt][3] *= a1;
        }
        __syncwarp();

        /* ---- P @ V ---- */
#pragma unroll
        for (int ks = 0; ks < 4; ks++) {
            const int kh = ks * 16 + 2 * gc;
            uint32_t pa[4];
            pa[0] = *(const uint32_t*)&Ps[row_l0 * PS + kh];
            pa[1] = *(const uint32_t*)&Ps[row_l1 * PS + kh];
            pa[2] = *(const uint32_t*)&Ps[row_l0 * PS + kh + 8];
            pa[3] = *(const uint32_t*)&Ps[row_l1 * PS + kh + 8];
#pragma unroll
            for (int nt = 0; nt < 16; nt++) {
                const int d = nt * 8 + gr;
                uint32_t b0 = *(const uint32_t*)&Vt[d * VS + kh];
                uint32_t b1 = *(const uint32_t*)&Vt[d * VS + kh + 8];
                mma_f16(O[nt], pa, b0, b1);
            }
        }
        __syncthreads();   /* stage s safe to overwrite next iteration */
    }

    /* normalize + store half */
    const float inv0 = 1.f / l0;
    const float inv1 = 1.f / l1;
    const int rg0 = qs + row_l0;
    const int rg1 = qs + row_l1;
#pragma unroll
    for (int nt = 0; nt < 16; nt++) {
        const int col = h * HD + nt * 8 + 2 * gc;
        if (rg0 < S_TOK)
            *(__half2*)&g_oh[(size_t)rg0 * DIM + col] = __floats2half2_rn(O[nt][0] * inv0, O[nt][1] * inv0);
        if (rg1 < S_TOK)
            *(__half2*)&g_oh[(size_t)rg1 * DIM + col] = __floats2half2_rn(O[nt][2] * inv1, O[nt][3] * inv1);
    }
}

/* ================= launch ================= */
extern "C" void kernel_launch(void* const* d_in, const int* in_sizes, int n_in,
                              void* d_out, int out_size)
{
    const float* x    = (const float*)d_in[0];
    const float* fcos = (const float*)d_in[3];
    const float* fsin = (const float*)d_in[4];
    const float* Wq = (const float*)d_in[5];  const float* bq = (const float*)d_in[6];
    const float* Wk = (const float*)d_in[7];  const float* bk = (const float*)d_in[8];
    const float* Wv = (const float*)d_in[9];  const float* bv = (const float*)d_in[10];
    const float* Wo = (const float*)d_in[11]; const float* bo = (const float*)d_in[12];
    const float* gq = (const float*)d_in[13]; const float* gk = (const float*)d_in[14];
    float* out = (float*)d_out;

    float *dq, *dk, *dv;
    __half *doh, *dxh, *dwTh;
    cudaGetSymbolAddress((void**)&dq,   g_q);
    cudaGetSymbolAddress((void**)&dk,   g_k);
    cudaGetSymbolAddress((void**)&dv,   g_v);
    cudaGetSymbolAddress((void**)&doh,  g_oh);
    cudaGetSymbolAddress((void**)&dxh,  g_xh);
    cudaGetSymbolAddress((void**)&dwTh, g_wTh);

    transpose_half_kernel<<<dim3(48, 48, 4), 256>>>(Wq, Wk, Wv, Wo, dwTh);
    convert_x_kernel<<<(S_TOK * DIM / 4 + 255) / 256, 256>>>(x);

    const dim3 gemm_grid(GK / BN, (S_TOK + BM - 1) / BM);

    gemm_f16_kernel<<<gemm_grid, 128>>>(dxh, dwTh + 0 * (size_t)GK * GK, bq, dq, S_TOK);
    gemm_f16_kernel<<<gemm_grid, 128>>>(dxh, dwTh + 1 * (size_t)GK * GK, bk, dk, S_TOK);
    gemm_f16_kernel<<<gemm_grid, 128>>>(dxh, dwTh + 2 * (size_t)GK * GK, bv, dv, S_TOK);

    rms_rope_kernel<<<dim3(S_TOK, 2), 256>>>(fcos, fsin, gq, gk);
    v_trans_kernel<<<dim3(VT_PAD / 32, DIM / 32), 256>>>();

    cudaFuncSetAttribute(attn_f16_kernel, cudaFuncAttributeMaxDynamicSharedMemorySize, ATTN_SMEM_BYTES);
    attn_f16_kernel<<<dim3((S_TOK + TQ2 - 1) / TQ2, NH), 256, ATTN_SMEM_BYTES>>>();

    gemm_f16_kernel<<<gemm_grid, 128>>>(doh, dwTh + 3 * (size_t)GK * GK, bo, out, S_TOK);
}

// round 8
// speedup vs baseline: 4.8306x; 1.0462x over previous
#include <cuda_runtime.h>
#include <cuda_fp16.h>
#include <math.h>
#include <stdint.h>

#define S_TOK 3120
#define DIM   1536
#define NH    12
#define HD    128
#define FRAME 520
#define TK    64
#define GK    1536
#define VT_PAD 3136   /* 49*64 */

/* ---- scratch (static device globals) ---- */
__device__ float  g_q[S_TOK * DIM];
__device__ float  g_k[S_TOK * DIM];
__device__ float  g_v[S_TOK * DIM];
__device__ __half g_oh[S_TOK * DIM];
__device__ __half g_xh[S_TOK * DIM];
__device__ __half g_wTh[4][GK * GK];
__device__ __half g_qhh[S_TOK * DIM];
__device__ __half g_qll[S_TOK * DIM];
__device__ __half g_khh[S_TOK * DIM];
__device__ __half g_kll[S_TOK * DIM];
__device__ __half g_vt[NH * HD * VT_PAD];

__device__ __forceinline__ void mma_f16(float* c, const uint32_t* a, uint32_t b0, uint32_t b1) {
    asm volatile(
        "mma.sync.aligned.m16n8k16.row.col.f32.f16.f16.f32 "
        "{%0,%1,%2,%3}, {%4,%5,%6,%7}, {%8,%9}, {%0,%1,%2,%3};"
        : "+f"(c[0]), "+f"(c[1]), "+f"(c[2]), "+f"(c[3])
        : "r"(a[0]), "r"(a[1]), "r"(a[2]), "r"(a[3]), "r"(b0), "r"(b1));
}

__device__ __forceinline__ void cp_async16(void* smem_dst, const void* gsrc, bool valid) {
    uint32_t saddr = (uint32_t)__cvta_generic_to_shared(smem_dst);
    int sz = valid ? 16 : 0;
    asm volatile("cp.async.cg.shared.global [%0], [%1], 16, %2;\n"
                 :: "r"(saddr), "l"(gsrc), "r"(sz));
}
__device__ __forceinline__ void cp_commit() { asm volatile("cp.async.commit_group;\n"); }
template <int N>
__device__ __forceinline__ void cp_wait() { asm volatile("cp.async.wait_group %0;\n" :: "n"(N)); }

/* ============== pre-pass kernels ============== */
__global__ __launch_bounds__(256) void transpose_half_kernel(
    const float* __restrict__ w0, const float* __restrict__ w1,
    const float* __restrict__ w2, const float* __restrict__ w3,
    __half* __restrict__ dstbase)
{
    __shared__ float tile[32][33];
    const float* src = (blockIdx.z == 0) ? w0 : (blockIdx.z == 1) ? w1 : (blockIdx.z == 2) ? w2 : w3;
    __half* dst = dstbase + (size_t)blockIdx.z * GK * GK;
    const int tx = threadIdx.x & 31, ty = threadIdx.x >> 5;
    int x = blockIdx.x * 32 + tx;
    int y = blockIdx.y * 32 + ty;
#pragma unroll
    for (int i = 0; i < 32; i += 8)
        tile[ty + i][tx] = src[(size_t)(y + i) * GK + x];
    __syncthreads();
    x = blockIdx.y * 32 + tx;
    y = blockIdx.x * 32 + ty;
#pragma unroll
    for (int i = 0; i < 32; i += 8)
        dst[(size_t)(y + i) * GK + x] = __float2half_rn(tile[tx][ty + i]);
}

__global__ __launch_bounds__(256) void convert_x_kernel(const float* __restrict__ x)
{
    int i = (blockIdx.x * 256 + threadIdx.x) * 4;
    if (i < S_TOK * DIM) {
        float4 v = *(const float4*)&x[i];
        *(__half2*)&g_xh[i]     = __floats2half2_rn(v.x, v.y);
        *(__half2*)&g_xh[i + 2] = __floats2half2_rn(v.z, v.w);
    }
}

__global__ __launch_bounds__(256) void v_trans_kernel()
{
    __shared__ float tile[32][33];
    const int tx = threadIdx.x & 31, ty = threadIdx.x >> 5;
    const int t0 = blockIdx.x * 32;
    const int d0 = blockIdx.y * 32;
#pragma unroll
    for (int i = 0; i < 32; i += 8) {
        const int tok = t0 + ty + i;
        tile[ty + i][tx] = (tok < S_TOK) ? g_v[(size_t)tok * DIM + d0 + tx] : 0.f;
    }
    __syncthreads();
#pragma unroll
    for (int i = 0; i < 32; i += 8) {
        const int d = d0 + ty + i;
        g_vt[(size_t)d * VT_PAD + t0 + tx] = __float2half_rn(tile[tx][ty + i]);
    }
}

/* ============== fp16 GEMM v2: 256 threads, 64x32 warp tiles ============== */
#define BM 128
#define BN 128
#define BKH 32
#define GST 40

__global__ __launch_bounds__(256, 2) void gemm_f16_kernel(
    const __half* __restrict__ A, const __half* __restrict__ Bt,
    const float* __restrict__ bias, float* __restrict__ C, int M)
{
    __shared__ __half As[2][BM][GST];
    __shared__ __half Bs[2][BN][GST];

    const int tid  = threadIdx.x;
    const int warp = tid >> 5;
    const int lane = tid & 31;
    const int gr   = lane >> 2;
    const int gc   = lane & 3;

    const int bm = blockIdx.y * BM;
    const int bn = blockIdx.x * BN;
    const int wm = (warp & 1) * 64;      /* 0 or 64  */
    const int wn = (warp >> 1) * 32;     /* 0..96    */

    float acc[4][4][4];
#pragma unroll
    for (int mi = 0; mi < 4; mi++)
#pragma unroll
        for (int nj = 0; nj < 4; nj++)
#pragma unroll
            for (int e = 0; e < 4; e++) acc[mi][nj][e] = 0.f;

    int crow[2]; int cc16[2];
#pragma unroll
    for (int i = 0; i < 2; i++) {
        const int cid = i * 256 + tid;
        crow[i] = cid >> 2;
        cc16[i] = cid & 3;
    }

    const int NT = GK / BKH;

#pragma unroll
    for (int i = 0; i < 2; i++) {
        cp_async16(&As[0][crow[i]][cc16[i] * 8], &A[(size_t)(bm + crow[i]) * GK + cc16[i] * 8], (bm + crow[i]) < M);
        cp_async16(&Bs[0][crow[i]][cc16[i] * 8], &Bt[(size_t)(bn + crow[i]) * GK + cc16[i] * 8], true);
    }
    cp_commit();

    for (int t = 0; t < NT; t++) {
        if (t + 1 < NT) {
            const int kt = (t + 1) * BKH;
            const int s1 = (t + 1) & 1;
#pragma unroll
            for (int i = 0; i < 2; i++) {
                cp_async16(&As[s1][crow[i]][cc16[i] * 8], &A[(size_t)(bm + crow[i]) * GK + kt + cc16[i] * 8], (bm + crow[i]) < M);
                cp_async16(&Bs[s1][crow[i]][cc16[i] * 8], &Bt[(size_t)(bn + crow[i]) * GK + kt + cc16[i] * 8], true);
            }
        }
        cp_commit();
        cp_wait<1>();
        __syncthreads();

        const int b = t & 1;
#pragma unroll
        for (int ks = 0; ks < 2; ks++) {
            const int kh = ks * 16 + 2 * gc;
            uint32_t af[4][4];
#pragma unroll
            for (int mi = 0; mi < 4; mi++) {
                const int m0 = wm + mi * 16 + gr;
                af[mi][0] = *(const uint32_t*)&As[b][m0][kh];
                af[mi][1] = *(const uint32_t*)&As[b][m0 + 8][kh];
                af[mi][2] = *(const uint32_t*)&As[b][m0][kh + 8];
                af[mi][3] = *(const uint32_t*)&As[b][m0 + 8][kh + 8];
            }
#pragma unroll
            for (int nj = 0; nj < 4; nj++) {
                const int n0 = wn + nj * 8 + gr;
                uint32_t b0 = *(const uint32_t*)&Bs[b][n0][kh];
                uint32_t b1 = *(const uint32_t*)&Bs[b][n0][kh + 8];
#pragma unroll
                for (int mi = 0; mi < 4; mi++)
                    mma_f16(acc[mi][nj], af[mi], b0, b1);
            }
        }
        __syncthreads();
    }

#pragma unroll
    for (int mi = 0; mi < 4; mi++) {
        const int row0 = bm + wm + mi * 16 + gr;
        const int row1 = row0 + 8;
#pragma unroll
        for (int nj = 0; nj < 4; nj++) {
            const int col = bn + wn + nj * 8 + 2 * gc;
            const float b0 = bias[col];
            const float b1 = bias[col + 1];
            if (row0 < M)
                *(float2*)&C[(size_t)row0 * GK + col] = make_float2(acc[mi][nj][0] + b0, acc[mi][nj][1] + b1);
            if (row1 < M)
                *(float2*)&C[(size_t)row1 * GK + col] = make_float2(acc[mi][nj][2] + b0, acc[mi][nj][3] + b1);
        }
    }
}

/* ============ fused RMSNorm + RoPE -> half hi/lo (unchanged) ============ */
__global__ __launch_bounds__(256) void rms_rope_kernel(
    const float* __restrict__ fcos, const float* __restrict__ fsin,
    const float* __restrict__ gq, const float* __restrict__ gk)
{
    const int row   = blockIdx.x;
    const int which = blockIdx.y;
    const float* buf = which ? g_k : g_q;
    __half* dh       = which ? g_khh : g_qhh;
    __half* dl       = which ? g_kll : g_qll;
    const float* g   = which ? gk : gq;
    const int tid    = threadIdx.x;

    const float* p = buf + (size_t)row * DIM;
    float ss = 0.f;
    for (int i = tid; i < DIM; i += 256) { float v = p[i]; ss += v * v; }

    __shared__ float red[256];
    red[tid] = ss;
    __syncthreads();
    for (int s = 128; s > 0; s >>= 1) {
        if (tid < s) red[tid] += red[tid + s];
        __syncthreads();
    }
    const float inv = rsqrtf(red[0] * (1.0f / DIM) + 1e-6f);

    const int f  = row / FRAME;
    const int hh = (row / 26) % 20;
    const int ww = row % 26;

    for (int pi = tid; pi < NH * 64; pi += 256) {
        const int head = pi >> 6;
        const int c    = pi & 63;
        const int pr   = (c < 22) ? f : ((c < 43) ? hh : ww);
        const float cs = fcos[pr * 64 + c];
        const float sn = fsin[pr * 64 + c];
        const size_t base = (size_t)row * DIM + head * HD + 2 * c;
        const float xr = buf[base]     * inv * g[head * HD + 2 * c];
        const float xi = buf[base + 1] * inv * g[head * HD + 2 * c + 1];
        const float r0 = xr * cs - xi * sn;
        const float r1 = xr * sn + xi * cs;
        const __half h0 = __float2half_rn(r0);
        const __half h1 = __float2half_rn(r1);
        *(__half2*)&dh[base] = __halves2half2(h0, h1);
        *(__half2*)&dl[base] = __floats2half2_rn(r0 - __half2float(h0), r1 - __half2float(h1));
    }
}

/* ========== fp16 flash attention: 128q x 64k, 2-term compensated QK ========== */
#define TQ2 128
#define QS 136
#define VS 72
#define PS 72
#define O_QH 0
#define O_QL (TQ2 * QS)
#define O_K  (2 * TQ2 * QS)
#define K_STG (2 * 64 * QS)
#define O_V  (O_K + 2 * K_STG)
#define V_STG (HD * VS)
#define O_P  (O_V + 2 * V_STG)
#define ATTN_HALVES (O_P + TQ2 * PS)
#define ATTN_SMEM_BYTES (ATTN_HALVES * 2)

__global__ __launch_bounds__(256) void attn_f16_kernel()
{
    extern __shared__ __half sh[];
    const int tid  = threadIdx.x;
    const int warp = tid >> 5;
    const int lane = tid & 31;
    const int gr   = lane >> 2;
    const int gc   = lane & 3;
    const int qs   = blockIdx.x * TQ2;
    const int h    = blockIdx.y;

#pragma unroll
    for (int i = 0; i < 8; i++) {
        const int id = i * 256 + tid;
        const int r = id >> 4, ch = id & 15;
        const bool v = (qs + r) < S_TOK;
        const size_t gsrc = (size_t)(qs + r) * DIM + h * HD + ch * 8;
        cp_async16(sh + O_QH + r * QS + ch * 8, &g_qhh[gsrc], v);
        cp_async16(sh + O_QL + r * QS + ch * 8, &g_qll[gsrc], v);
    }

    const int fi_min = qs / FRAME;
    const int fi_max = min(qs + TQ2 - 1, S_TOK - 1) / FRAME;
    int lo = fi_min - 3; if (lo < 0) lo = 0;
    lo *= FRAME;
    int hi = (fi_max + 1) * FRAME; if (hi > S_TOK) hi = S_TOK;
    int tiles[52]; int ntile = 0;
    if (lo <= FRAME) {
        for (int ks = 0; ks < hi; ks += TK) tiles[ntile++] = ks;
    } else {
        for (int ks = 0; ks < FRAME; ks += TK) tiles[ntile++] = ks;
        for (int ks = (lo / TK) * TK; ks < hi; ks += TK) tiles[ntile++] = ks;
    }

    auto load_kv = [&](int ks, int s) {
        __half* Khp = sh + O_K + s * K_STG;
        __half* Klp = Khp + 64 * QS;
        __half* Vp  = sh + O_V + s * V_STG;
#pragma unroll
        for (int i = 0; i < 4; i++) {
            const int id = i * 256 + tid;
            const int r = id >> 4, ch = id & 15;
            const bool v = (ks + r) < S_TOK;
            const size_t gsrc = (size_t)(ks + r) * DIM + h * HD + ch * 8;
            cp_async16(Khp + r * QS + ch * 8, &g_khh[gsrc], v);
            cp_async16(Klp + r * QS + ch * 8, &g_kll[gsrc], v);
        }
#pragma unroll
        for (int i = 0; i < 4; i++) {
            const int id = i * 256 + tid;
            const int d = id >> 3, ch = id & 7;
            cp_async16(Vp + d * VS + ch * 8, &g_vt[(size_t)(h * HD + d) * VT_PAD + ks + ch * 8], true);
        }
    };

    load_kv(tiles[0], 0);
    cp_commit();

    const int row_l0 = warp * 16 + gr;
    const int row_l1 = row_l0 + 8;
    const int fi0 = (qs + row_l0) / FRAME;
    const int fi1 = (qs + row_l1) / FRAME;

    float m0 = -1e30f, m1 = -1e30f, l0 = 0.f, l1 = 0.f;
    float O[16][4];
#pragma unroll
    for (int nt = 0; nt < 16; nt++)
#pragma unroll
        for (int e = 0; e < 4; e++) O[nt][e] = 0.f;

    const float scale = 0.08838834764831845f;
    const __half* Qh = sh + O_QH;
    const __half* Ql = sh + O_QL;
    __half* Ps = sh + O_P;

    for (int it = 0; it < ntile; it++) {
        const int s = it & 1;
        if (it + 1 < ntile) load_kv(tiles[it + 1], s ^ 1);
        cp_commit();
        cp_wait<1>();
        __syncthreads();

        const int ks0 = tiles[it];
        const __half* Kh = sh + O_K + s * K_STG;
        const __half* Vt = sh + O_V + s * V_STG;

        /* ---- QK^T (2-term compensated fp16: qh*kh + ql*kh) ---- */
        float Sa[8][4];
#pragma unroll
        for (int nj = 0; nj < 8; nj++)
#pragma unroll
            for (int e = 0; e < 4; e++) Sa[nj][e] = 0.f;

#pragma unroll
        for (int ks = 0; ks < 8; ks++) {
            const int kh = ks * 16 + 2 * gc;
            uint32_t ah[4], al[4];
            ah[0] = *(const uint32_t*)&Qh[row_l0 * QS + kh];
            ah[1] = *(const uint32_t*)&Qh[row_l1 * QS + kh];
            ah[2] = *(const uint32_t*)&Qh[row_l0 * QS + kh + 8];
            ah[3] = *(const uint32_t*)&Qh[row_l1 * QS + kh + 8];
            al[0] = *(const uint32_t*)&Ql[row_l0 * QS + kh];
            al[1] = *(const uint32_t*)&Ql[row_l1 * QS + kh];
            al[2] = *(const uint32_t*)&Ql[row_l0 * QS + kh + 8];
            al[3] = *(const uint32_t*)&Ql[row_l1 * QS + kh + 8];
#pragma unroll
            for (int nj = 0; nj < 8; nj++) {
                const int n = nj * 8 + gr;
                uint32_t bh0 = *(const uint32_t*)&Kh[n * QS + kh];
                uint32_t bh1 = *(const uint32_t*)&Kh[n * QS + kh + 8];
                mma_f16(Sa[nj], ah, bh0, bh1);
                mma_f16(Sa[nj], al, bh0, bh1);
            }
        }

        /* ---- scale + frame mask ---- */
        float mloc0 = -1e30f, mloc1 = -1e30f;
#pragma unroll
        for (int nj = 0; nj < 8; nj++) {
            const int cg = ks0 + nj * 8 + 2 * gc;
            const int fj = cg / FRAME;
            const bool kv = (cg < S_TOK);
            const bool ok0 = kv && (fj <= fi0) && (((fi0 - fj) < 4) || (fj == 0));
            const bool ok1 = kv && (fj <= fi1) && (((fi1 - fj) < 4) || (fj == 0));
            Sa[nj][0] = ok0 ? Sa[nj][0] * scale : -1e30f;
            Sa[nj][1] = ok0 ? Sa[nj][1] * scale : -1e30f;
            Sa[nj][2] = ok1 ? Sa[nj][2] * scale : -1e30f;
            Sa[nj][3] = ok1 ? Sa[nj][3] * scale : -1e30f;
            mloc0 = fmaxf(mloc0, fmaxf(Sa[nj][0], Sa[nj][1]));
            mloc1 = fmaxf(mloc1, fmaxf(Sa[nj][2], Sa[nj][3]));
        }
        mloc0 = fmaxf(mloc0, __shfl_xor_sync(0xffffffffu, mloc0, 1));
        mloc0 = fmaxf(mloc0, __shfl_xor_sync(0xffffffffu, mloc0, 2));
        mloc1 = fmaxf(mloc1, __shfl_xor_sync(0xffffffffu, mloc1, 1));
        mloc1 = fmaxf(mloc1, __shfl_xor_sync(0xffffffffu, mloc1, 2));

        const float mn0 = fmaxf(m0, mloc0);
        const float mn1 = fmaxf(m1, mloc1);
        const float a0 = __expf(m0 - mn0);
        const float a1 = __expf(m1 - mn1);
        m0 = mn0; m1 = mn1;

        float ls0 = 0.f, ls1 = 0.f;
#pragma unroll
        for (int nj = 0; nj < 8; nj++) {
            const int cc = nj * 8 + 2 * gc;
            float p00 = __expf(Sa[nj][0] - mn0);
            float p01 = __expf(Sa[nj][1] - mn0);
            float p10 = __expf(Sa[nj][2] - mn1);
            float p11 = __expf(Sa[nj][3] - mn1);
            ls0 += p00 + p01;
            ls1 += p10 + p11;
            *(__half2*)&Ps[row_l0 * PS + cc] = __floats2half2_rn(p00, p01);
            *(__half2*)&Ps[row_l1 * PS + cc] = __floats2half2_rn(p10, p11);
        }
        ls0 += __shfl_xor_sync(0xffffffffu, ls0, 1);
        ls0 += __shfl_xor_sync(0xffffffffu, ls0, 2);
        ls1 += __shfl_xor_sync(0xffffffffu, ls1, 1);
        ls1 += __shfl_xor_sync(0xffffffffu, ls1, 2);
        l0 = l0 * a0 + ls0;
        l1 = l1 * a1 + ls1;

#pragma unroll
        for (int nt = 0; nt < 16; nt++) {
            O[nt][0] *= a0; O[nt][1] *= a0;
            O[nt][2] *= a1; O[nt][3] *= a1;
        }
        __syncwarp();

        /* ---- P @ V ---- */
#pragma unroll
        for (int ks = 0; ks < 4; ks++) {
            const int kh = ks * 16 + 2 * gc;
            uint32_t pa[4];
            pa[0] = *(const uint32_t*)&Ps[row_l0 * PS + kh];
            pa[1] = *(const uint32_t*)&Ps[row_l1 * PS + kh];
            pa[2] = *(const uint32_t*)&Ps[row_l0 * PS + kh + 8];
            pa[3] = *(const uint32_t*)&Ps[row_l1 * PS + kh + 8];
#pragma unroll
            for (int nt = 0; nt < 16; nt++) {
                const int d = nt * 8 + gr;
                uint32_t b0 = *(const uint32_t*)&Vt[d * VS + kh];
                uint32_t b1 = *(const uint32_t*)&Vt[d * VS + kh + 8];
                mma_f16(O[nt], pa, b0, b1);
            }
        }
        __syncthreads();
    }

    const float inv0 = 1.f / l0;
    const float inv1 = 1.f / l1;
    const int rg0 = qs + row_l0;
    const int rg1 = qs + row_l1;
#pragma unroll
    for (int nt = 0; nt < 16; nt++) {
        const int col = h * HD + nt * 8 + 2 * gc;
        if (rg0 < S_TOK)
            *(__half2*)&g_oh[(size_t)rg0 * DIM + col] = __floats2half2_rn(O[nt][0] * inv0, O[nt][1] * inv0);
        if (rg1 < S_TOK)
            *(__half2*)&g_oh[(size_t)rg1 * DIM + col] = __floats2half2_rn(O[nt][2] * inv1, O[nt][3] * inv1);
    }
}

/* ================= launch ================= */
extern "C" void kernel_launch(void* const* d_in, const int* in_sizes, int n_in,
                              void* d_out, int out_size)
{
    const float* x    = (const float*)d_in[0];
    const float* fcos = (const float*)d_in[3];
    const float* fsin = (const float*)d_in[4];
    const float* Wq = (const float*)d_in[5];  const float* bq = (const float*)d_in[6];
    const float* Wk = (const float*)d_in[7];  const float* bk = (const float*)d_in[8];
    const float* Wv = (const float*)d_in[9];  const float* bv = (const float*)d_in[10];
    const float* Wo = (const float*)d_in[11]; const float* bo = (const float*)d_in[12];
    const float* gq = (const float*)d_in[13]; const float* gk = (const float*)d_in[14];
    float* out = (float*)d_out;

    float *dq, *dk, *dv;
    __half *doh, *dxh, *dwTh;
    cudaGetSymbolAddress((void**)&dq,   g_q);
    cudaGetSymbolAddress((void**)&dk,   g_k);
    cudaGetSymbolAddress((void**)&dv,   g_v);
    cudaGetSymbolAddress((void**)&doh,  g_oh);
    cudaGetSymbolAddress((void**)&dxh,  g_xh);
    cudaGetSymbolAddress((void**)&dwTh, g_wTh);

    transpose_half_kernel<<<dim3(48, 48, 4), 256>>>(Wq, Wk, Wv, Wo, dwTh);
    convert_x_kernel<<<(S_TOK * DIM / 4 + 255) / 256, 256>>>(x);

    const dim3 gemm_grid(GK / BN, (S_TOK + BM - 1) / BM);

    gemm_f16_kernel<<<gemm_grid, 256>>>(dxh, dwTh + 0 * (size_t)GK * GK, bq, dq, S_TOK);
    gemm_f16_kernel<<<gemm_grid, 256>>>(dxh, dwTh + 1 * (size_t)GK * GK, bk, dk, S_TOK);
    gemm_f16_kernel<<<gemm_grid, 256>>>(dxh, dwTh + 2 * (size_t)GK * GK, bv, dv, S_TOK);

    rms_rope_kernel<<<dim3(S_TOK, 2), 256>>>(fcos, fsin, gq, gk);
    v_trans_kernel<<<dim3(VT_PAD / 32, DIM / 32), 256>>>();

    cudaFuncSetAttribute(attn_f16_kernel, cudaFuncAttributeMaxDynamicSharedMemorySize, ATTN_SMEM_BYTES);
    attn_f16_kernel<<<dim3((S_TOK + TQ2 - 1) / TQ2, NH), 256, ATTN_SMEM_BYTES>>>();

    gemm_f16_kernel<<<gemm_grid, 256>>>(doh, dwTh + 3 * (size_t)GK * GK, bo, out, S_TOK);
}

// round 10
// speedup vs baseline: 5.1611x; 1.0684x over previous
#include <cuda_runtime.h>
#include <cuda_fp16.h>
#include <math.h>
#include <stdint.h>

#define S_TOK 3120
#define DIM   1536
#define NH    12
#define HD    128
#define FRAME 520
#define TK    64
#define GK    1536
#define VT_PAD 3136   /* 49*64 */

/* ---- scratch (static device globals) ---- */
__device__ float  g_q[S_TOK * DIM];
__device__ float  g_k[S_TOK * DIM];
__device__ float  g_v[S_TOK * DIM];
__device__ __half g_oh[S_TOK * DIM];
__device__ __half g_xh[S_TOK * DIM];
__device__ __half g_wTh[4][GK * GK];
__device__ __half g_qhh[S_TOK * DIM];
__device__ __half g_qll[S_TOK * DIM];
__device__ __half g_khh[S_TOK * DIM];
__device__ __half g_kll[S_TOK * DIM];
__device__ __half g_vt[NH * HD * VT_PAD];

__device__ __forceinline__ void mma_f16(float* c, const uint32_t* a, uint32_t b0, uint32_t b1) {
    asm volatile(
        "mma.sync.aligned.m16n8k16.row.col.f32.f16.f16.f32 "
        "{%0,%1,%2,%3}, {%4,%5,%6,%7}, {%8,%9}, {%0,%1,%2,%3};"
        : "+f"(c[0]), "+f"(c[1]), "+f"(c[2]), "+f"(c[3])
        : "r"(a[0]), "r"(a[1]), "r"(a[2]), "r"(a[3]), "r"(b0), "r"(b1));
}

__device__ __forceinline__ void cp_async16(void* smem_dst, const void* gsrc, bool valid) {
    uint32_t saddr = (uint32_t)__cvta_generic_to_shared(smem_dst);
    int sz = valid ? 16 : 0;
    asm volatile("cp.async.cg.shared.global [%0], [%1], 16, %2;\n"
                 :: "r"(saddr), "l"(gsrc), "r"(sz));
}
__device__ __forceinline__ void cp_commit() { asm volatile("cp.async.commit_group;\n"); }
template <int N>
__device__ __forceinline__ void cp_wait() { asm volatile("cp.async.wait_group %0;\n" :: "n"(N)); }

/* ============== pre-pass kernels ============== */
__global__ __launch_bounds__(256) void transpose_half_kernel(
    const float* __restrict__ w0, const float* __restrict__ w1,
    const float* __restrict__ w2, const float* __restrict__ w3,
    __half* __restrict__ dstbase)
{
    __shared__ float tile[32][33];
    const float* src = (blockIdx.z == 0) ? w0 : (blockIdx.z == 1) ? w1 : (blockIdx.z == 2) ? w2 : w3;
    __half* dst = dstbase + (size_t)blockIdx.z * GK * GK;
    const int tx = threadIdx.x & 31, ty = threadIdx.x >> 5;
    int x = blockIdx.x * 32 + tx;
    int y = blockIdx.y * 32 + ty;
#pragma unroll
    for (int i = 0; i < 32; i += 8)
        tile[ty + i][tx] = src[(size_t)(y + i) * GK + x];
    __syncthreads();
    x = blockIdx.y * 32 + tx;
    y = blockIdx.x * 32 + ty;
#pragma unroll
    for (int i = 0; i < 32; i += 8)
        dst[(size_t)(y + i) * GK + x] = __float2half_rn(tile[tx][ty + i]);
}

__global__ __launch_bounds__(256) void convert_x_kernel(const float* __restrict__ x)
{
    int i = (blockIdx.x * 256 + threadIdx.x) * 4;
    if (i < S_TOK * DIM) {
        float4 v = *(const float4*)&x[i];
        *(__half2*)&g_xh[i]     = __floats2half2_rn(v.x, v.y);
        *(__half2*)&g_xh[i + 2] = __floats2half2_rn(v.z, v.w);
    }
}

__global__ __launch_bounds__(256) void v_trans_kernel()
{
    __shared__ float tile[32][33];
    const int tx = threadIdx.x & 31, ty = threadIdx.x >> 5;
    const int t0 = blockIdx.x * 32;
    const int d0 = blockIdx.y * 32;
#pragma unroll
    for (int i = 0; i < 32; i += 8) {
        const int tok = t0 + ty + i;
        tile[ty + i][tx] = (tok < S_TOK) ? g_v[(size_t)tok * DIM + d0 + tx] : 0.f;
    }
    __syncthreads();
#pragma unroll
    for (int i = 0; i < 32; i += 8) {
        const int d = d0 + ty + i;
        g_vt[(size_t)d * VT_PAD + t0 + tx] = __float2half_rn(tile[tx][ty + i]);
    }
}

/* ============== fp16 GEMM core (R7 config: 128 thr, 64x64 warp tiles) ============== */
#define BM 128
#define BN 128
#define BKH 32
#define GST 40

__device__ __forceinline__ void gemm_body(
    const __half* __restrict__ A, const __half* __restrict__ Bt,
    const float* __restrict__ bias, float* __restrict__ C,
    int bm, int bn, int M)
{
    __shared__ __half As[2][BM][GST];
    __shared__ __half Bs[2][BN][GST];

    const int tid  = threadIdx.x;
    const int warp = tid >> 5;
    const int lane = tid & 31;
    const int gr   = lane >> 2;
    const int gc   = lane & 3;

    const int wm = (warp & 1) * 64;
    const int wn = (warp >> 1) * 64;

    float acc[4][8][4];
#pragma unroll
    for (int mi = 0; mi < 4; mi++)
#pragma unroll
        for (int nj = 0; nj < 8; nj++)
#pragma unroll
            for (int e = 0; e < 4; e++) acc[mi][nj][e] = 0.f;

    int crow[4]; int cc16[4];
#pragma unroll
    for (int i = 0; i < 4; i++) {
        const int cid = i * 128 + tid;
        crow[i] = cid >> 2;
        cc16[i] = cid & 3;
    }

    const int NT = GK / BKH;

#pragma unroll
    for (int i = 0; i < 4; i++) {
        cp_async16(&As[0][crow[i]][cc16[i] * 8], &A[(size_t)(bm + crow[i]) * GK + cc16[i] * 8], (bm + crow[i]) < M);
        cp_async16(&Bs[0][crow[i]][cc16[i] * 8], &Bt[(size_t)(bn + crow[i]) * GK + cc16[i] * 8], true);
    }
    cp_commit();

    for (int t = 0; t < NT; t++) {
        if (t + 1 < NT) {
            const int kt = (t + 1) * BKH;
            const int s1 = (t + 1) & 1;
#pragma unroll
            for (int i = 0; i < 4; i++) {
                cp_async16(&As[s1][crow[i]][cc16[i] * 8], &A[(size_t)(bm + crow[i]) * GK + kt + cc16[i] * 8], (bm + crow[i]) < M);
                cp_async16(&Bs[s1][crow[i]][cc16[i] * 8], &Bt[(size_t)(bn + crow[i]) * GK + kt + cc16[i] * 8], true);
            }
        }
        cp_commit();
        cp_wait<1>();
        __syncthreads();

        const int b = t & 1;
#pragma unroll
        for (int ks = 0; ks < 2; ks++) {
            const int kh = ks * 16 + 2 * gc;
            uint32_t af[4][4];
#pragma unroll
            for (int mi = 0; mi < 4; mi++) {
                const int m0 = wm + mi * 16 + gr;
                af[mi][0] = *(const uint32_t*)&As[b][m0][kh];
                af[mi][1] = *(const uint32_t*)&As[b][m0 + 8][kh];
                af[mi][2] = *(const uint32_t*)&As[b][m0][kh + 8];
                af[mi][3] = *(const uint32_t*)&As[b][m0 + 8][kh + 8];
            }
#pragma unroll
            for (int nj = 0; nj < 8; nj++) {
                const int n0 = wn + nj * 8 + gr;
                uint32_t b0 = *(const uint32_t*)&Bs[b][n0][kh];
                uint32_t b1 = *(const uint32_t*)&Bs[b][n0][kh + 8];
#pragma unroll
                for (int mi = 0; mi < 4; mi++)
                    mma_f16(acc[mi][nj], af[mi], b0, b1);
            }
        }
        __syncthreads();
    }

#pragma unroll
    for (int mi = 0; mi < 4; mi++) {
        const int row0 = bm + wm + mi * 16 + gr;
        const int row1 = row0 + 8;
#pragma unroll
        for (int nj = 0; nj < 8; nj++) {
            const int col = bn + wn + nj * 8 + 2 * gc;
            const float b0 = bias[col];
            const float b1 = bias[col + 1];
            if (row0 < M)
                *(float2*)&C[(size_t)row0 * GK + col] = make_float2(acc[mi][nj][0] + b0, acc[mi][nj][1] + b1);
            if (row1 < M)
                *(float2*)&C[(size_t)row1 * GK + col] = make_float2(acc[mi][nj][2] + b0, acc[mi][nj][3] + b1);
        }
    }
}

/* fused QKV GEMM: grid.x covers 3*GK columns; selects W/bias/output by column third */
__global__ __launch_bounds__(128, 2) void gemm_qkv_kernel(
    const float* __restrict__ bq, const float* __restrict__ bk, const float* __restrict__ bv)
{
    const int bng = blockIdx.x * BN;          /* 0..4607 */
    const int which = bng / GK;
    const int bn = bng - which * GK;
    const __half* Bt = &g_wTh[which][0];
    const float* bias = (which == 0) ? bq : (which == 1) ? bk : bv;
    float* C = (which == 0) ? g_q : (which == 1) ? g_k : g_v;
    gemm_body(g_xh, Bt, bias, C, blockIdx.y * BM, bn, S_TOK);
}

__global__ __launch_bounds__(128, 2) void gemm_out_kernel(
    const float* __restrict__ bias, float* __restrict__ C)
{
    gemm_body(g_oh, &g_wTh[3][0], bias, C, blockIdx.y * BM, blockIdx.x * BN, S_TOK);
}

/* ============ fused RMSNorm + RoPE -> half hi/lo ============ */
__global__ __launch_bounds__(256) void rms_rope_kernel(
    const float* __restrict__ fcos, const float* __restrict__ fsin,
    const float* __restrict__ gq, const float* __restrict__ gk)
{
    const int row   = blockIdx.x;
    const int which = blockIdx.y;
    const float* buf = which ? g_k : g_q;
    __half* dh       = which ? g_khh : g_qhh;
    __half* dl       = which ? g_kll : g_qll;
    const float* g   = which ? gk : gq;
    const int tid    = threadIdx.x;

    const float* p = buf + (size_t)row * DIM;
    float ss = 0.f;
    for (int i = tid; i < DIM; i += 256) { float v = p[i]; ss += v * v; }

    __shared__ float red[256];
    red[tid] = ss;
    __syncthreads();
    for (int s = 128; s > 0; s >>= 1) {
        if (tid < s) red[tid] += red[tid + s];
        __syncthreads();
    }
    const float inv = rsqrtf(red[0] * (1.0f / DIM) + 1e-6f);

    const int f  = row / FRAME;
    const int hh = (row / 26) % 20;
    const int ww = row % 26;

    for (int pi = tid; pi < NH * 64; pi += 256) {
        const int head = pi >> 6;
        const int c    = pi & 63;
        const int pr   = (c < 22) ? f : ((c < 43) ? hh : ww);
        const float cs = fcos[pr * 64 + c];
        const float sn = fsin[pr * 64 + c];
        const size_t base = (size_t)row * DIM + head * HD + 2 * c;
        const float xr = buf[base]     * inv * g[head * HD + 2 * c];
        const float xi = buf[base + 1] * inv * g[head * HD + 2 * c + 1];
        const float r0 = xr * cs - xi * sn;
        const float r1 = xr * sn + xi * cs;
        const __half h0 = __float2half_rn(r0);
        const __half h1 = __float2half_rn(r1);
        *(__half2*)&dh[base] = __halves2half2(h0, h1);
        *(__half2*)&dl[base] = __floats2half2_rn(r0 - __half2float(h0), r1 - __half2float(h1));
    }
}

/* ========== fp16 flash attention: 128q x 64k, 2-term compensated QK ========== */
#define TQ2 128
#define QS 136
#define VS 72
#define PS 72
#define O_QH 0
#define O_QL (TQ2 * QS)
#define O_K  (2 * TQ2 * QS)
#define K_STG (2 * 64 * QS)
#define O_V  (O_K + 2 * K_STG)
#define V_STG (HD * VS)
#define O_P  (O_V + 2 * V_STG)
#define ATTN_HALVES (O_P + TQ2 * PS)
#define ATTN_SMEM_BYTES (ATTN_HALVES * 2)

__global__ __launch_bounds__(256) void attn_f16_kernel()
{
    extern __shared__ __half sh[];
    const int tid  = threadIdx.x;
    const int warp = tid >> 5;
    const int lane = tid & 31;
    const int gr   = lane >> 2;
    const int gc   = lane & 3;
    const int qs   = blockIdx.x * TQ2;
    const int h    = blockIdx.y;

#pragma unroll
    for (int i = 0; i < 8; i++) {
        const int id = i * 256 + tid;
        const int r = id >> 4, ch = id & 15;
        const bool v = (qs + r) < S_TOK;
        const size_t gsrc = (size_t)(qs + r) * DIM + h * HD + ch * 8;
        cp_async16(sh + O_QH + r * QS + ch * 8, &g_qhh[gsrc], v);
        cp_async16(sh + O_QL + r * QS + ch * 8, &g_qll[gsrc], v);
    }

    const int fi_min = qs / FRAME;
    const int fi_max = min(qs + TQ2 - 1, S_TOK - 1) / FRAME;
    int lo = fi_min - 3; if (lo < 0) lo = 0;
    lo *= FRAME;
    int hi = (fi_max + 1) * FRAME; if (hi > S_TOK) hi = S_TOK;
    int tiles[52]; int ntile = 0;
    if (lo <= FRAME) {
        for (int ks = 0; ks < hi; ks += TK) tiles[ntile++] = ks;
    } else {
        for (int ks = 0; ks < FRAME; ks += TK) tiles[ntile++] = ks;
        for (int ks = (lo / TK) * TK; ks < hi; ks += TK) tiles[ntile++] = ks;
    }

    auto load_kv = [&](int ks, int s) {
        __half* Khp = sh + O_K + s * K_STG;
        __half* Klp = Khp + 64 * QS;
        __half* Vp  = sh + O_V + s * V_STG;
#pragma unroll
        for (int i = 0; i < 4; i++) {
            const int id = i * 256 + tid;
            const int r = id >> 4, ch = id & 15;
            const bool v = (ks + r) < S_TOK;
            const size_t gsrc = (size_t)(ks + r) * DIM + h * HD + ch * 8;
            cp_async16(Khp + r * QS + ch * 8, &g_khh[gsrc], v);
            cp_async16(Klp + r * QS + ch * 8, &g_kll[gsrc], v);
        }
#pragma unroll
        for (int i = 0; i < 4; i++) {
            const int id = i * 256 + tid;
            const int d = id >> 3, ch = id & 7;
            cp_async16(Vp + d * VS + ch * 8, &g_vt[(size_t)(h * HD + d) * VT_PAD + ks + ch * 8], true);
        }
    };

    load_kv(tiles[0], 0);
    cp_commit();

    const int row_l0 = warp * 16 + gr;
    const int row_l1 = row_l0 + 8;
    const int fi0 = (qs + row_l0) / FRAME;
    const int fi1 = (qs + row_l1) / FRAME;

    float m0 = -1e30f, m1 = -1e30f, l0 = 0.f, l1 = 0.f;
    float O[16][4];
#pragma unroll
    for (int nt = 0; nt < 16; nt++)
#pragma unroll
        for (int e = 0; e < 4; e++) O[nt][e] = 0.f;

    const float scale = 0.08838834764831845f;
    const __half* Qh = sh + O_QH;
    const __half* Ql = sh + O_QL;
    __half* Ps = sh + O_P;

    for (int it = 0; it < ntile; it++) {
        const int s = it & 1;
        if (it + 1 < ntile) load_kv(tiles[it + 1], s ^ 1);
        cp_commit();
        cp_wait<1>();
        __syncthreads();

        const int ks0 = tiles[it];
        const __half* Kh = sh + O_K + s * K_STG;
        const __half* Vt = sh + O_V + s * V_STG;

        float Sa[8][4];
#pragma unroll
        for (int nj = 0; nj < 8; nj++)
#pragma unroll
            for (int e = 0; e < 4; e++) Sa[nj][e] = 0.f;

#pragma unroll
        for (int ks = 0; ks < 8; ks++) {
            const int kh = ks * 16 + 2 * gc;
            uint32_t ah[4], al[4];
            ah[0] = *(const uint32_t*)&Qh[row_l0 * QS + kh];
            ah[1] = *(const uint32_t*)&Qh[row_l1 * QS + kh];
            ah[2] = *(const uint32_t*)&Qh[row_l0 * QS + kh + 8];
            ah[3] = *(const uint32_t*)&Qh[row_l1 * QS + kh + 8];
            al[0] = *(const uint32_t*)&Ql[row_l0 * QS + kh];
            al[1] = *(const uint32_t*)&Ql[row_l1 * QS + kh];
            al[2] = *(const uint32_t*)&Ql[row_l0 * QS + kh + 8];
            al[3] = *(const uint32_t*)&Ql[row_l1 * QS + kh + 8];
#pragma unroll
            for (int nj = 0; nj < 8; nj++) {
                const int n = nj * 8 + gr;
                uint32_t bh0 = *(const uint32_t*)&Kh[n * QS + kh];
                uint32_t bh1 = *(const uint32_t*)&Kh[n * QS + kh + 8];
                mma_f16(Sa[nj], ah, bh0, bh1);
                mma_f16(Sa[nj], al, bh0, bh1);
            }
        }

        float mloc0 = -1e30f, mloc1 = -1e30f;
#pragma unroll
        for (int nj = 0; nj < 8; nj++) {
            const int cg = ks0 + nj * 8 + 2 * gc;
            const int fj = cg / FRAME;
            const bool kv = (cg < S_TOK);
            const bool ok0 = kv && (fj <= fi0) && (((fi0 - fj) < 4) || (fj == 0));
            const bool ok1 = kv && (fj <= fi1) && (((fi1 - fj) < 4) || (fj == 0));
            Sa[nj][0] = ok0 ? Sa[nj][0] * scale : -1e30f;
            Sa[nj][1] = ok0 ? Sa[nj][1] * scale : -1e30f;
            Sa[nj][2] = ok1 ? Sa[nj][2] * scale : -1e30f;
            Sa[nj][3] = ok1 ? Sa[nj][3] * scale : -1e30f;
            mloc0 = fmaxf(mloc0, fmaxf(Sa[nj][0], Sa[nj][1]));
            mloc1 = fmaxf(mloc1, fmaxf(Sa[nj][2], Sa[nj][3]));
        }
        mloc0 = fmaxf(mloc0, __shfl_xor_sync(0xffffffffu, mloc0, 1));
        mloc0 = fmaxf(mloc0, __shfl_xor_sync(0xffffffffu, mloc0, 2));
        mloc1 = fmaxf(mloc1, __shfl_xor_sync(0xffffffffu, mloc1, 1));
        mloc1 = fmaxf(mloc1, __shfl_xor_sync(0xffffffffu, mloc1, 2));

        const float mn0 = fmaxf(m0, mloc0);
        const float mn1 = fmaxf(m1, mloc1);
        const float a0 = __expf(m0 - mn0);
        const float a1 = __expf(m1 - mn1);
        m0 = mn0; m1 = mn1;

        float ls0 = 0.f, ls1 = 0.f;
#pragma unroll
        for (int nj = 0; nj < 8; nj++) {
            const int cc = nj * 8 + 2 * gc;
            float p00 = __expf(Sa[nj][0] - mn0);
            float p01 = __expf(Sa[nj][1] - mn0);
            float p10 = __expf(Sa[nj][2] - mn1);
            float p11 = __expf(Sa[nj][3] - mn1);
            ls0 += p00 + p01;
            ls1 += p10 + p11;
            *(__half2*)&Ps[row_l0 * PS + cc] = __floats2half2_rn(p00, p01);
            *(__half2*)&Ps[row_l1 * PS + cc] = __floats2half2_rn(p10, p11);
        }
        ls0 += __shfl_xor_sync(0xffffffffu, ls0, 1);
        ls0 += __shfl_xor_sync(0xffffffffu, ls0, 2);
        ls1 += __shfl_xor_sync(0xffffffffu, ls1, 1);
        ls1 += __shfl_xor_sync(0xffffffffu, ls1, 2);
        l0 = l0 * a0 + ls0;
        l1 = l1 * a1 + ls1;

#pragma unroll
        for (int nt = 0; nt < 16; nt++) {
            O[nt][0] *= a0; O[nt][1] *= a0;
            O[nt][2] *= a1; O[nt][3] *= a1;
        }
        __syncwarp();

#pragma unroll
        for (int ks = 0; ks < 4; ks++) {
            const int kh = ks * 16 + 2 * gc;
            uint32_t pa[4];
            pa[0] = *(const uint32_t*)&Ps[row_l0 * PS + kh];
            pa[1] = *(const uint32_t*)&Ps[row_l1 * PS + kh];
            pa[2] = *(const uint32_t*)&Ps[row_l0 * PS + kh + 8];
            pa[3] = *(const uint32_t*)&Ps[row_l1 * PS + kh + 8];
#pragma unroll
            for (int nt = 0; nt < 16; nt++) {
                const int d = nt * 8 + gr;
                uint32_t b0 = *(const uint32_t*)&Vt[d * VS + kh];
                uint32_t b1 = *(const uint32_t*)&Vt[d * VS + kh + 8];
                mma_f16(O[nt], pa, b0, b1);
            }
        }
        __syncthreads();
    }

    const float inv0 = 1.f / l0;
    const float inv1 = 1.f / l1;
    const int rg0 = qs + row_l0;
    const int rg1 = qs + row_l1;
#pragma unroll
    for (int nt = 0; nt < 16; nt++) {
        const int col = h * HD + nt * 8 + 2 * gc;
        if (rg0 < S_TOK)
            *(__half2*)&g_oh[(size_t)rg0 * DIM + col] = __floats2half2_rn(O[nt][0] * inv0, O[nt][1] * inv0);
        if (rg1 < S_TOK)
            *(__half2*)&g_oh[(size_t)rg1 * DIM + col] = __floats2half2_rn(O[nt][2] * inv1, O[nt][3] * inv1);
    }
}

/* ================= launch ================= */
extern "C" void kernel_launch(void* const* d_in, const int* in_sizes, int n_in,
                              void* d_out, int out_size)
{
    const float* x    = (const float*)d_in[0];
    const float* fcos = (const float*)d_in[3];
    const float* fsin = (const float*)d_in[4];
    const float* Wq = (const float*)d_in[5];  const float* bq = (const float*)d_in[6];
    const float* Wk = (const float*)d_in[7];  const float* bk = (const float*)d_in[8];
    const float* Wv = (const float*)d_in[9];  const float* bv = (const float*)d_in[10];
    const float* Wo = (const float*)d_in[11]; const float* bo = (const float*)d_in[12];
    const float* gq = (const float*)d_in[13]; const float* gk = (const float*)d_in[14];
    float* out = (float*)d_out;

    __half *dwTh;
    cudaGetSymbolAddress((void**)&dwTh, g_wTh);

    transpose_half_kernel<<<dim3(48, 48, 4), 256>>>(Wq, Wk, Wv, Wo, dwTh);
    convert_x_kernel<<<(S_TOK * DIM / 4 + 255) / 256, 256>>>(x);

    /* fused QKV GEMM: 36 column tiles x 25 row tiles = 900 CTAs (3.04 waves) */
    gemm_qkv_kernel<<<dim3(3 * GK / BN, (S_TOK + BM - 1) / BM), 128>>>(bq, bk, bv);

    rms_rope_kernel<<<dim3(S_TOK, 2), 256>>>(fcos, fsin, gq, gk);
    v_trans_kernel<<<dim3(VT_PAD / 32, DIM / 32), 256>>>();

    cudaFuncSetAttribute(attn_f16_kernel, cudaFuncAttributeMaxDynamicSharedMemorySize, ATTN_SMEM_BYTES);
    attn_f16_kernel<<<dim3((S_TOK + TQ2 - 1) / TQ2, NH), 256, ATTN_SMEM_BYTES>>>();

    gemm_out_kernel<<<dim3(GK / BN, (S_TOK + BM - 1) / BM), 128>>>(bo, out);
}